// round 11
// baseline (speedup 1.0000x reference)
#include <cuda_runtime.h>
#include <cuda_bf16.h>
#include <math.h>
#include <float.h>
#include <stdint.h>

#define NN 50000
#define EE 400000
#define EPP 40000
#define FF 64
#define EDD 32
#define HH 128
#define LLAYERS 2

// ---------------- scratch ----------------
__device__ float g_x   [(size_t)NN*HH];
__device__ float g_ea  [(size_t)EE*HH];
__device__ float g_h   [(size_t)EE*HH];
__device__ float g_pin [(size_t)NN*13*HH];
__device__ float g_tmp [(size_t)NN*HH];
__device__ float g_out [(size_t)NN*HH];
__device__ float g_pa  [(size_t)NN*HH];
__device__ float g_pb  [(size_t)NN*HH];
__device__ float g_bnsum[HH];
__device__ float g_bnss [HH];
__device__ float g_zerov[HH];
__device__ float g_bc  [LLAYERS*HH];

// CSR / permutation
__device__ int g_cnt   [NN];
__device__ int g_rowptr[NN + 1];
__device__ int g_wr    [NN];
__device__ int g_eord  [EE];
__device__ int g_psrc  [EE];
__device__ int g_pdst  [EE];
__device__ int g_blksum[64];

// transposed + hi/lo split weights  [N=128][K] bf16
__device__ __nv_bfloat16 g_wn_hi [(size_t)128*64];
__device__ __nv_bfloat16 g_wn_lo [(size_t)128*64];
__device__ __nv_bfloat16 g_we_hi [(size_t)128*32];
__device__ __nv_bfloat16 g_we_lo [(size_t)128*32];
__device__ __nv_bfloat16 g_wc_hi [(size_t)LLAYERS*128*128];
__device__ __nv_bfloat16 g_wc_lo [(size_t)LLAYERS*128*128];
__device__ __nv_bfloat16 g_w1_hi [(size_t)LLAYERS*128*128];
__device__ __nv_bfloat16 g_w1_lo [(size_t)LLAYERS*128*128];
__device__ __nv_bfloat16 g_w2_hi [(size_t)LLAYERS*128*128];
__device__ __nv_bfloat16 g_w2_lo [(size_t)LLAYERS*128*128];
__device__ __nv_bfloat16 g_u1_hi [(size_t)LLAYERS*128*128];
__device__ __nv_bfloat16 g_u1_lo [(size_t)LLAYERS*128*128];
__device__ __nv_bfloat16 g_u2_hi [(size_t)LLAYERS*128*128];
__device__ __nv_bfloat16 g_u2_lo [(size_t)LLAYERS*128*128];
__device__ __nv_bfloat16 g_u3_hi [(size_t)LLAYERS*128*128];
__device__ __nv_bfloat16 g_u3_lo [(size_t)LLAYERS*128*128];
__device__ __nv_bfloat16 g_em2_hi[(size_t)LLAYERS*128*128];
__device__ __nv_bfloat16 g_em2_lo[(size_t)LLAYERS*128*128];
__device__ __nv_bfloat16 g_po_hi [(size_t)LLAYERS*128*1664];
__device__ __nv_bfloat16 g_po_lo [(size_t)LLAYERS*128*1664];
__device__ __nv_bfloat16 g_li_hi [(size_t)LLAYERS*128*128];
__device__ __nv_bfloat16 g_li_lo [(size_t)LLAYERS*128*128];

// ---------------- mma.sync helpers ----------------
__device__ __forceinline__ uint32_t smem_u32(const void* p) {
    uint32_t a;
    asm("{ .reg .u64 t; cvta.to.shared.u64 t, %1; cvt.u32.u64 %0, t; }" : "=r"(a) : "l"(p));
    return a;
}
__device__ __forceinline__ void ldsm4(uint32_t r[4], uint32_t addr) {
    asm volatile("ldmatrix.sync.aligned.m8n8.x4.shared.b16 {%0,%1,%2,%3}, [%4];"
                 : "=r"(r[0]), "=r"(r[1]), "=r"(r[2]), "=r"(r[3]) : "r"(addr));
}
__device__ __forceinline__ void mma16816(float c[4], const uint32_t a[4],
                                         uint32_t b0, uint32_t b1) {
    asm volatile("mma.sync.aligned.m16n8k16.row.col.f32.bf16.bf16.f32 "
                 "{%0,%1,%2,%3}, {%4,%5,%6,%7}, {%8,%9}, {%0,%1,%2,%3};"
                 : "+f"(c[0]), "+f"(c[1]), "+f"(c[2]), "+f"(c[3])
                 : "r"(a[0]), "r"(a[1]), "r"(a[2]), "r"(a[3]), "r"(b0), "r"(b1));
}
// fast hi/lo split: hi = truncate-to-bf16 (PRMT), lo = exact remainder rounded to bf16
__device__ __forceinline__ void cvt2(float2 f, uint32_t& h, uint32_t& l) {
    uint32_t b0 = __float_as_uint(f.x);
    uint32_t b1 = __float_as_uint(f.y);
    h = __byte_perm(b0, b1, 0x7632);
    float l0 = f.x - __uint_as_float(b0 & 0xFFFF0000u);
    float l1 = f.y - __uint_as_float(b1 & 0xFFFF0000u);
    __nv_bfloat162 p = __floats2bfloat162_rn(l0, l1);
    l = *reinterpret_cast<uint32_t*>(&p);
}

#define PITCH 80
#define CHB   10240

// ---------------- sync-free resident-B GEMM (K <= 128), NT tiles/block ----------
// Depth-2 rolling A-prefetch: 8 independent LDG.64 in flight per thread.
template<int K, int EPI, bool GATHER, int NT>
__global__ __launch_bounds__(256, 2) void tcgN(
    const float* __restrict__ A, const int* __restrict__ gidx,
    const __nv_bfloat16* __restrict__ Whi, const __nv_bfloat16* __restrict__ Wlo,
    const float* __restrict__ bias,
    const float* __restrict__ G1, const int* __restrict__ idx1,
    const float* __restrict__ G2, const int* __restrict__ idx2,
    float* __restrict__ C, int M)
{
    constexpr int NCH = K / 32;
    constexpr int NST = 2 * NCH;
    extern __shared__ __align__(16) uint8_t sB[];
    uint8_t* sBhi = sB;
    uint8_t* sBlo = sB + NCH * CHB;

    const int tid = threadIdx.x;
    const int wid = tid >> 5;
    const int lid = tid & 31;

    {
        const int frow = tid >> 1;
        const int fkh  = (tid & 1) * 16;
#pragma unroll
        for (int c = 0; c < NCH; c++) {
            const __nv_bfloat16* sh = Whi + (size_t)frow * K + c * 32 + fkh;
            const __nv_bfloat16* sl = Wlo + (size_t)frow * K + c * 32 + fkh;
            const uint32_t off = c * CHB + frow * PITCH + fkh * 2;
            *(uint4*)(sBhi + off)      = *(const uint4*)sh;
            *(uint4*)(sBhi + off + 16) = *(const uint4*)(sh + 8);
            *(uint4*)(sBlo + off)      = *(const uint4*)sl;
            *(uint4*)(sBlo + off + 16) = *(const uint4*)(sl + 8);
        }
    }
    __syncthreads();   // only barrier; B read-only afterwards

    const int q   = lid >> 2;
    const int c2  = (lid & 3) * 2;
    const int r8 = lid & 7, jj = lid >> 3;
    const uint32_t offB = (uint32_t)(((jj >> 1) * 8 + r8) * PITCH + (jj & 1) * 16);
    const uint32_t uBhi = smem_u32(sBhi);
    const uint32_t uBlo = smem_u32(sBlo);

    for (int t = 0; t < NT; t++) {
        const int m0 = (blockIdx.x * NT + t) * 128;
        const int r0g = m0 + wid * 16 + q;
        int ar0 = min(r0g,     M - 1);
        int ar1 = min(r0g + 8, M - 1);
        if (GATHER) { ar0 = gidx[ar0]; ar1 = gidx[ar1]; }
        const float* Arow0 = A + (size_t)ar0 * K;
        const float* Arow1 = A + (size_t)ar1 * K;

        float acc[16][4];
#pragma unroll
        for (int j = 0; j < 16; j++)
#pragma unroll
            for (int i = 0; i < 4; i++) acc[j][i] = 0.f;

        // depth-2 prefetch buffers
        float2 buf0[4], buf1[4];
        {
            const int k0 = c2;
            buf0[0] = *(const float2*)(Arow0 + k0);
            buf0[1] = *(const float2*)(Arow1 + k0);
            buf0[2] = *(const float2*)(Arow0 + k0 + 8);
            buf0[3] = *(const float2*)(Arow1 + k0 + 8);
        }
        if (NST > 1) {
            const int k0 = 16 + c2;
            buf1[0] = *(const float2*)(Arow0 + k0);
            buf1[1] = *(const float2*)(Arow1 + k0);
            buf1[2] = *(const float2*)(Arow0 + k0 + 8);
            buf1[3] = *(const float2*)(Arow1 + k0 + 8);
        }

#pragma unroll
        for (int step = 0; step < NST; step++) {
            float2* cb = (step & 1) ? buf1 : buf0;
            uint32_t ah[4], al[4];
            cvt2(cb[0], ah[0], al[0]);
            cvt2(cb[1], ah[1], al[1]);
            cvt2(cb[2], ah[2], al[2]);
            cvt2(cb[3], ah[3], al[3]);
            if (step + 2 < NST) {
                const int k0 = (step + 2) * 16 + c2;
                cb[0] = *(const float2*)(Arow0 + k0);
                cb[1] = *(const float2*)(Arow1 + k0);
                cb[2] = *(const float2*)(Arow0 + k0 + 8);
                cb[3] = *(const float2*)(Arow1 + k0 + 8);
            }
            const uint32_t cbase = (uint32_t)(step >> 1) * CHB;
            const uint32_t kso   = (uint32_t)(step & 1) * 32;
#pragma unroll
            for (int nb = 0; nb < 8; nb++) {
                uint32_t bh[4], bl[4];
                ldsm4(bh, uBhi + cbase + offB + nb * (16 * PITCH) + kso);
                ldsm4(bl, uBlo + cbase + offB + nb * (16 * PITCH) + kso);
                mma16816(acc[2 * nb],     ah, bh[0], bh[1]);
                mma16816(acc[2 * nb + 1], ah, bh[2], bh[3]);
                mma16816(acc[2 * nb],     ah, bl[0], bl[1]);
                mma16816(acc[2 * nb + 1], ah, bl[2], bl[3]);
                mma16816(acc[2 * nb],     al, bh[0], bh[1]);
                mma16816(acc[2 * nb + 1], al, bh[2], bh[3]);
            }
        }

#pragma unroll
        for (int h = 0; h < 2; h++) {
            const int r = m0 + wid * 16 + q + h * 8;
            if (r < M) {
                const float* g1 = nullptr;
                const float* g2 = nullptr;
                if (EPI >= 3) {
                    g1 = G1 + (size_t)idx1[r] * HH;
                    g2 = G2 + (size_t)idx2[r] * HH;
                }
                float* cp = C + (size_t)r * HH;
#pragma unroll
                for (int j = 0; j < 16; j++) {
                    const int n0 = j * 8 + c2;
                    float v0 = acc[j][h * 2 + 0] + bias[n0];
                    float v1 = acc[j][h * 2 + 1] + bias[n0 + 1];
                    if (EPI >= 3) {
                        v0 += g1[n0] + g2[n0];
                        v1 += g1[n0 + 1] + g2[n0 + 1];
                    }
                    if (EPI == 4) { v0 = fmaxf(v0, 0.f); v1 = fmaxf(v1, 0.f); }
                    if (EPI == 2) {
                        float2 prev = *(float2*)(cp + n0);
                        v0 = prev.x + 0.5f * v0;
                        v1 = prev.y + 0.5f * v1;
                    }
                    *(float2*)(cp + n0) = make_float2(v0, v1);
                }
            }
        }
    }
}

// ---------------- dual-output resident-B GEMM (K=128, 512 thr) ----------------
__global__ __launch_bounds__(512) void tcgN_dual(
    const float* __restrict__ A,
    const __nv_bfloat16* __restrict__ W1hi, const __nv_bfloat16* __restrict__ W1lo,
    const __nv_bfloat16* __restrict__ W2hi, const __nv_bfloat16* __restrict__ W2lo,
    const float* __restrict__ b1, const float* __restrict__ b2,
    float* __restrict__ C1, float* __restrict__ C2, int M)
{
    constexpr int K = 128, NCH = 4;
    extern __shared__ __align__(16) uint8_t sB[];
    const int tid = threadIdx.x;
    const int wid = tid >> 5;
    const int lid = tid & 31;
    const int m0  = blockIdx.x * 128;

    {
        const int frow = tid >> 2;
        const int fq   = tid & 3;
        const uint32_t wo = (uint32_t)frow * PITCH + fq * 16;
#pragma unroll
        for (int w = 0; w < 2; w++) {
            const __nv_bfloat16* Whi = w ? W2hi : W1hi;
            const __nv_bfloat16* Wlo = w ? W2lo : W1lo;
            uint8_t* dh = sB + w * (8 * CHB);
            uint8_t* dl = dh + 4 * CHB;
#pragma unroll
            for (int c = 0; c < NCH; c++) {
                const __nv_bfloat16* sh = Whi + (size_t)frow * K + c * 32 + fq * 8;
                const __nv_bfloat16* sl = Wlo + (size_t)frow * K + c * 32 + fq * 8;
                *(uint4*)(dh + c * CHB + wo) = *(const uint4*)sh;
                *(uint4*)(dl + c * CHB + wo) = *(const uint4*)sl;
            }
        }
    }
    __syncthreads();

    const int wsel = wid >> 3;
    const int w8   = wid & 7;
    const int q  = lid >> 2;
    const int c2 = (lid & 3) * 2;
    const int r0g = m0 + w8 * 16 + q;
    const size_t rc0 = (size_t)min(r0g,     M - 1);
    const size_t rc1 = (size_t)min(r0g + 8, M - 1);
    const float* Arow0 = A + rc0 * K;
    const float* Arow1 = A + rc1 * K;

    const int r8 = lid & 7, jj = lid >> 3;
    const uint32_t offB = (uint32_t)(((jj >> 1) * 8 + r8) * PITCH + (jj & 1) * 16);
    const uint32_t uBhi = smem_u32(sB) + wsel * (8 * CHB);
    const uint32_t uBlo = uBhi + 4 * CHB;

    float acc[16][4];
#pragma unroll
    for (int j = 0; j < 16; j++)
#pragma unroll
        for (int i = 0; i < 4; i++) acc[j][i] = 0.f;

    float2 pf0, pf1, pf2, pf3;
    pf0 = *(const float2*)(Arow0 + c2);
    pf1 = *(const float2*)(Arow1 + c2);
    pf2 = *(const float2*)(Arow0 + c2 + 8);
    pf3 = *(const float2*)(Arow1 + c2 + 8);
#pragma unroll
    for (int step = 0; step < 8; step++) {
        uint32_t ah[4], al[4];
        cvt2(pf0, ah[0], al[0]);
        cvt2(pf1, ah[1], al[1]);
        cvt2(pf2, ah[2], al[2]);
        cvt2(pf3, ah[3], al[3]);
        if (step + 1 < 8) {
            const int k0 = (step + 1) * 16 + c2;
            pf0 = *(const float2*)(Arow0 + k0);
            pf1 = *(const float2*)(Arow1 + k0);
            pf2 = *(const float2*)(Arow0 + k0 + 8);
            pf3 = *(const float2*)(Arow1 + k0 + 8);
        }
        const uint32_t cb  = (uint32_t)(step >> 1) * CHB;
        const uint32_t kso = (uint32_t)(step & 1) * 32;
#pragma unroll
        for (int nb = 0; nb < 8; nb++) {
            uint32_t bh[4], bl[4];
            ldsm4(bh, uBhi + cb + offB + nb * (16 * PITCH) + kso);
            ldsm4(bl, uBlo + cb + offB + nb * (16 * PITCH) + kso);
            mma16816(acc[2 * nb],     ah, bh[0], bh[1]);
            mma16816(acc[2 * nb + 1], ah, bh[2], bh[3]);
            mma16816(acc[2 * nb],     ah, bl[0], bl[1]);
            mma16816(acc[2 * nb + 1], ah, bl[2], bl[3]);
            mma16816(acc[2 * nb],     al, bh[0], bh[1]);
            mma16816(acc[2 * nb + 1], al, bh[2], bh[3]);
        }
    }

    const float* bias = wsel ? b2 : b1;
    float* C = wsel ? C2 : C1;
#pragma unroll
    for (int h = 0; h < 2; h++) {
        const int r = m0 + w8 * 16 + q + h * 8;
        if (r < M) {
            float* cp = C + (size_t)r * HH;
#pragma unroll
            for (int j = 0; j < 16; j++) {
                const int n0 = j * 8 + c2;
                *(float2*)(cp + n0) = make_float2(acc[j][h * 2 + 0] + bias[n0],
                                                  acc[j][h * 2 + 1] + bias[n0 + 1]);
            }
        }
    }
}

// ---------------- chunked pipeline GEMM (K=1664: post) ----------------
template<int K>
__global__ __launch_bounds__(256) void tcg_big(
    const float* __restrict__ A,
    const __nv_bfloat16* __restrict__ Whi, const __nv_bfloat16* __restrict__ Wlo,
    const float* __restrict__ bias, float* __restrict__ C, int M)
{
    __shared__ __align__(16) uint8_t sAhi[128 * PITCH];
    __shared__ __align__(16) uint8_t sAlo[128 * PITCH];
    __shared__ __align__(16) uint8_t sBhi[128 * PITCH];
    __shared__ __align__(16) uint8_t sBlo[128 * PITCH];

    const int tid = threadIdx.x;
    const int wid = tid >> 5;
    const int lid = tid & 31;
    const int m0  = blockIdx.x * 128;

    const int frow = tid >> 1;
    const int fkh  = (tid & 1) * 16;
    const int ar   = min(m0 + frow, M - 1);
    const float* aRow = A + (size_t)ar * K;
    const __nv_bfloat16* bhRow = Whi + (size_t)frow * K;
    const __nv_bfloat16* blRow = Wlo + (size_t)frow * K;
    uint8_t* aHiDst = sAhi + frow * PITCH + fkh * 2;
    uint8_t* aLoDst = sAlo + frow * PITCH + fkh * 2;
    uint8_t* bHiDst = sBhi + frow * PITCH + fkh * 2;
    uint8_t* bLoDst = sBlo + frow * PITCH + fkh * 2;

    const int r8 = lid & 7, jj = lid >> 3;
    const uint32_t offA = (uint32_t)(((jj & 1) * 8 + r8 + wid * 16) * PITCH + (jj >> 1) * 16);
    const uint32_t offB = (uint32_t)(((jj >> 1) * 8 + r8) * PITCH + (jj & 1) * 16);
    const uint32_t uAhi = smem_u32(sAhi), uAlo = smem_u32(sAlo);
    const uint32_t uBhi = smem_u32(sBhi), uBlo = smem_u32(sBlo);

    float acc[16][4];
#pragma unroll
    for (int j = 0; j < 16; j++)
#pragma unroll
        for (int i = 0; i < 4; i++) acc[j][i] = 0.f;

    for (int kc = 0; kc < K; kc += 32) {
        float4 f0 = *(const float4*)(aRow + kc + fkh + 0);
        float4 f1 = *(const float4*)(aRow + kc + fkh + 4);
        float4 f2 = *(const float4*)(aRow + kc + fkh + 8);
        float4 f3 = *(const float4*)(aRow + kc + fkh + 12);
        uint4 bh0 = *(const uint4*)(bhRow + kc + fkh);
        uint4 bh1 = *(const uint4*)(bhRow + kc + fkh + 8);
        uint4 bl0 = *(const uint4*)(blRow + kc + fkh);
        uint4 bl1 = *(const uint4*)(blRow + kc + fkh + 8);

        float f[16] = {f0.x, f0.y, f0.z, f0.w, f1.x, f1.y, f1.z, f1.w,
                       f2.x, f2.y, f2.z, f2.w, f3.x, f3.y, f3.z, f3.w};
        uint32_t hw[8], lw[8];
#pragma unroll
        for (int i = 0; i < 8; i++) {
            float2 p = make_float2(f[2 * i], f[2 * i + 1]);
            cvt2(p, hw[i], lw[i]);
        }

        __syncthreads();
        *(uint4*)(aHiDst)      = make_uint4(hw[0], hw[1], hw[2], hw[3]);
        *(uint4*)(aHiDst + 16) = make_uint4(hw[4], hw[5], hw[6], hw[7]);
        *(uint4*)(aLoDst)      = make_uint4(lw[0], lw[1], lw[2], lw[3]);
        *(uint4*)(aLoDst + 16) = make_uint4(lw[4], lw[5], lw[6], lw[7]);
        *(uint4*)(bHiDst)      = bh0;
        *(uint4*)(bHiDst + 16) = bh1;
        *(uint4*)(bLoDst)      = bl0;
        *(uint4*)(bLoDst + 16) = bl1;
        __syncthreads();

#pragma unroll
        for (int ks = 0; ks < 2; ks++) {
            const uint32_t kso = ks * 32;
            uint32_t ah[4], al[4];
            ldsm4(ah, uAhi + offA + kso);
            ldsm4(al, uAlo + offA + kso);
#pragma unroll
            for (int nb = 0; nb < 8; nb++) {
                uint32_t bh[4], bl[4];
                ldsm4(bh, uBhi + offB + nb * (16 * PITCH) + kso);
                ldsm4(bl, uBlo + offB + nb * (16 * PITCH) + kso);
                mma16816(acc[2 * nb],     ah, bh[0], bh[1]);
                mma16816(acc[2 * nb + 1], ah, bh[2], bh[3]);
                mma16816(acc[2 * nb],     ah, bl[0], bl[1]);
                mma16816(acc[2 * nb + 1], ah, bl[2], bl[3]);
                mma16816(acc[2 * nb],     al, bh[0], bh[1]);
                mma16816(acc[2 * nb + 1], al, bh[2], bh[3]);
            }
        }
    }

    const int q  = lid >> 2;
    const int c2 = (lid & 3) * 2;
#pragma unroll
    for (int h = 0; h < 2; h++) {
        const int r = m0 + wid * 16 + q + h * 8;
        if (r < M) {
            float* cp = C + (size_t)r * HH;
#pragma unroll
            for (int j = 0; j < 16; j++) {
                const int n0 = j * 8 + c2;
                *(float2*)(cp + n0) = make_float2(acc[j][h * 2 + 0] + bias[n0],
                                                  acc[j][h * 2 + 1] + bias[n0 + 1]);
            }
        }
    }
}

// ---------------- batched weight prep ----------------
#define NJOBS 17
struct PrepJobs {
    const float* W[NJOBS];
    __nv_bfloat16* hi[NJOBS];
    __nv_bfloat16* lo[NJOBS];
    int K[NJOBS];
};
__global__ void prep_all_kernel(PrepJobs jobs) {
    const int job = blockIdx.y;
    const int K = jobs.K[job];
    const int i = blockIdx.x * 256 + threadIdx.x;
    if (i >= K * 128) return;
    const int k = i >> 7, n = i & 127;
    float w = jobs.W[job][i];
    __nv_bfloat16 h = __float2bfloat16(w);
    float rem = w - __bfloat162float(h);
    jobs.hi[job][(size_t)n * K + k] = h;
    jobs.lo[job][(size_t)n * K + k] = __float2bfloat16(rem);
}

__global__ void combine_wc_kernel(const float* __restrict__ eenc_w,
                                  const float* __restrict__ pre_w,
                                  __nv_bfloat16* __restrict__ hi,
                                  __nv_bfloat16* __restrict__ lo) {
    const int l = blockIdx.y;
    const float* ew = eenc_w + (size_t)l * 128 * 128;
    const float* W3 = pre_w + (size_t)l * 384 * 128 + 256 * 128;
    int i = blockIdx.x * blockDim.x + threadIdx.x;
    int k = i >> 7, n = i & 127;
    float s = 0.f;
    for (int j = 0; j < 128; j++) s += ew[k * 128 + j] * W3[j * 128 + n];
    __nv_bfloat16 h = __float2bfloat16(s);
    float rem = s - __bfloat162float(h);
    size_t o = (size_t)l * 128 * 128;
    hi[o + (size_t)n * 128 + k] = h;
    lo[o + (size_t)n * 128 + k] = __float2bfloat16(rem);
}
__global__ void combine_bc_kernel(const float* __restrict__ eenc_b,
                                  const float* __restrict__ pre_w,
                                  const float* __restrict__ pre_b,
                                  float* __restrict__ bc, float* __restrict__ zv) {
    const int l = blockIdx.x;
    const float* W3 = pre_w + (size_t)l * 384 * 128 + 256 * 128;
    int n = threadIdx.x;
    float s = pre_b[l * 128 + n];
    for (int j = 0; j < 128; j++) s += eenc_b[l * 128 + j] * W3[j * 128 + n];
    bc[l * 128 + n] = s;
    if (l == 0) zv[n] = 0.f;
}

// ---------------- CSR build + edge permutation ----------------
__global__ void zero_cnt_we_kernel(const float* __restrict__ We) {
    int i = blockIdx.x * blockDim.x + threadIdx.x;
    if (i < NN) g_cnt[i] = 0;
    if (i < EDD * 128) {
        int k = i >> 7, n = i & 127;
        float w = We[i];
        __nv_bfloat16 h = __float2bfloat16(w);
        float rem = w - __bfloat162float(h);
        g_we_hi[(size_t)n * EDD + k] = h;
        g_we_lo[(size_t)n * EDD + k] = __float2bfloat16(rem);
    }
}
__global__ void hist_kernel(const int* __restrict__ dst) {
    int e = blockIdx.x * blockDim.x + threadIdx.x;
    if (e < EE) atomicAdd(&g_cnt[dst[e]], 1);
}
__global__ void scan1_kernel() {
    __shared__ int s[1024];
    int t = threadIdx.x, i = blockIdx.x * 1024 + t;
    int v = (i < NN) ? g_cnt[i] : 0;
    s[t] = v;
    __syncthreads();
    for (int off = 1; off < 1024; off <<= 1) {
        int y = (t >= off) ? s[t - off] : 0;
        __syncthreads();
        s[t] += y;
        __syncthreads();
    }
    if (i < NN) g_rowptr[i] = s[t] - v;
    if (t == 1023) g_blksum[blockIdx.x] = s[1023];
}
__global__ void scan23_kernel() {
    __shared__ int base;
    if (threadIdx.x == 0) {
        int run = 0;
        for (int b = 0; b < (int)blockIdx.x; b++) run += g_blksum[b];
        base = run;
    }
    __syncthreads();
    int i = blockIdx.x * 1024 + threadIdx.x;
    if (i < NN) {
        int r = g_rowptr[i] + base;
        g_rowptr[i] = r;
        g_wr[i] = r;
    }
    if (i == 0) g_rowptr[NN] = EE;
}
__global__ void scatter_kernel(const int* __restrict__ src, const int* __restrict__ dst) {
    int e = blockIdx.x * blockDim.x + threadIdx.x;
    if (e < EE) {
        int d = dst[e];
        int o = atomicAdd(&g_wr[d], 1);
        g_eord[o] = e;
        g_psrc[o] = src[e];
        g_pdst[o] = d;
    }
}

// ---------------- fused streaming segmented reduce + pin build (256 thr, MLP) ----
__global__ __launch_bounds__(256) void agg_pin_kernel(const float* __restrict__ adl_ptr) {
    __shared__ float s_sum[128], s_ss[128], s_mn[128], s_mx[128];
    const int n = blockIdx.x;
    const int c = threadIdx.x & 127;
    const int s = threadIdx.x >> 7;          // 0 or 1: row-stride split
    const int a = g_rowptr[n], b = g_rowptr[n + 1];

    float sum = 0.f, ss = 0.f, mn = FLT_MAX, mx = -FLT_MAX;
    int i = a + s;
    // unroll-4: 4 independent loads in flight (rows i, i+2, i+4, i+6)
    for (; i + 6 < b; i += 8) {
        float v0 = g_h[(size_t)(i    ) * HH + c];
        float v1 = g_h[(size_t)(i + 2) * HH + c];
        float v2 = g_h[(size_t)(i + 4) * HH + c];
        float v3 = g_h[(size_t)(i + 6) * HH + c];
        sum += v0 + v1 + v2 + v3;
        ss  += v0 * v0 + v1 * v1 + v2 * v2 + v3 * v3;
        mn = fminf(mn, fminf(fminf(v0, v1), fminf(v2, v3)));
        mx = fmaxf(mx, fmaxf(fmaxf(v0, v1), fmaxf(v2, v3)));
    }
    for (; i < b; i += 2) {
        float v = g_h[(size_t)i * HH + c];
        sum += v; ss += v * v;
        mn = fminf(mn, v); mx = fmaxf(mx, v);
    }

    if (s == 1) { s_sum[c] = sum; s_ss[c] = ss; s_mn[c] = mn; s_mx[c] = mx; }
    __syncthreads();
    if (s == 1) return;
    sum += s_sum[c];
    ss  += s_ss[c];
    mn = fminf(mn, s_mn[c]);
    mx = fmaxf(mx, s_mx[c]);

    float deg  = (float)(b - a);
    float degc = fmaxf(deg, 1.f);
    float adl  = *adl_ptr;
    float logd = logf(degc + 1.f);
    float amp  = logd / adl;
    float att  = adl / logd;
    if (deg <= 0.f) { mn = 0.f; mx = 0.f; }
    float mean = sum / degc;
    float var  = ss / degc - mean * mean;
    float stdv = sqrtf(fmaxf(var, 0.f) + 1e-5f);
    float* r = g_pin + (size_t)n * (13 * HH);
    r[0 * HH + c]  = g_x[(size_t)n * HH + c];
    r[1 * HH + c]  = mean;
    r[2 * HH + c]  = mn;
    r[3 * HH + c]  = mx;
    r[4 * HH + c]  = stdv;
    r[5 * HH + c]  = mean * amp;
    r[6 * HH + c]  = mn * amp;
    r[7 * HH + c]  = mx * amp;
    r[8 * HH + c]  = stdv * amp;
    r[9 * HH + c]  = mean * att;
    r[10 * HH + c] = mn * att;
    r[11 * HH + c] = mx * att;
    r[12 * HH + c] = stdv * att;
}

// ---------------- batchnorm + residual ----------------
__global__ void bn_zero_kernel() {
    if (threadIdx.x < HH) { g_bnsum[threadIdx.x] = 0.f; g_bnss[threadIdx.x] = 0.f; }
}
__global__ void bn_reduce_kernel() {
    int c  = threadIdx.x;
    int r0 = blockIdx.x * 128;
    int r1 = min(r0 + 128, NN);
    float s = 0.f, ss = 0.f;
    for (int r = r0; r < r1; r++) {
        float v = g_out[(size_t)r * HH + c];
        s += v; ss += v * v;
    }
    atomicAdd(&g_bnsum[c], s);
    atomicAdd(&g_bnss[c], ss);
}
__global__ void bn_apply_kernel(const float* __restrict__ gamma,
                                const float* __restrict__ beta,
                                float* __restrict__ xout) {
    size_t idx = (size_t)blockIdx.x * blockDim.x + threadIdx.x;
    if (idx >= (size_t)NN * HH) return;
    int c = (int)(idx & 127);
    float mu  = g_bnsum[c] / (float)NN;
    float var = g_bnss[c] / (float)NN - mu * mu;
    float v = gamma[c] * (g_out[idx] - mu) * rsqrtf(var + 1e-5f) + beta[c];
    float r = (g_x[idx] + fmaxf(v, 0.f)) * 0.5f;
    g_x[idx] = r;
    if (xout) xout[idx] = r;
}

// ---------------- launch ----------------
extern "C" void kernel_launch(void* const* d_in, const int* in_sizes, int n_in,
                              void* d_out, int out_size) {
    (void)in_sizes; (void)n_in; (void)out_size;

    const float* x_in     = (const float*)d_in[0];
    const int*   ei       = (const int*)  d_in[1];
    const float* eattr    = (const float*)d_in[2];
    const float* pos_attr = (const float*)d_in[4];
    const float* neg_attr = (const float*)d_in[6];
    const float* adl      = (const float*)d_in[7];
    const float* Wnode    = (const float*)d_in[8];
    const float* bnode    = (const float*)d_in[9];
    const float* Wedge    = (const float*)d_in[10];
    const float* bedge    = (const float*)d_in[11];
    const float* eenc_w   = (const float*)d_in[12];
    const float* eenc_b   = (const float*)d_in[13];
    const float* pre_w    = (const float*)d_in[14];
    const float* pre_b    = (const float*)d_in[15];
    const float* post_w   = (const float*)d_in[16];
    const float* post_b   = (const float*)d_in[17];
    const float* lin_w    = (const float*)d_in[18];
    const float* lin_b    = (const float*)d_in[19];
    const float* emlp_w1  = (const float*)d_in[20];
    const float* emlp_b1  = (const float*)d_in[21];
    const float* emlp_w2  = (const float*)d_in[22];
    const float* emlp_b2  = (const float*)d_in[23];
    const float* bng      = (const float*)d_in[24];
    const float* bnb      = (const float*)d_in[25];

    const int* src = ei;
    const int* dst = ei + EE;

    float* outx   = (float*)d_out;
    float* outpos = outx + (size_t)NN * HH;
    float* outneg = outpos + (size_t)EPP * HH;

    float *p_x, *p_ea, *p_h, *p_pin, *p_tmp, *p_out, *p_pa, *p_pb, *p_zero, *p_bc;
    cudaGetSymbolAddress((void**)&p_x,    g_x);
    cudaGetSymbolAddress((void**)&p_ea,   g_ea);
    cudaGetSymbolAddress((void**)&p_h,    g_h);
    cudaGetSymbolAddress((void**)&p_pin,  g_pin);
    cudaGetSymbolAddress((void**)&p_tmp,  g_tmp);
    cudaGetSymbolAddress((void**)&p_out,  g_out);
    cudaGetSymbolAddress((void**)&p_pa,   g_pa);
    cudaGetSymbolAddress((void**)&p_pb,   g_pb);
    cudaGetSymbolAddress((void**)&p_zero, g_zerov);
    cudaGetSymbolAddress((void**)&p_bc,   g_bc);

    int *p_eord, *p_psrc, *p_pdst;
    cudaGetSymbolAddress((void**)&p_eord, g_eord);
    cudaGetSymbolAddress((void**)&p_psrc, g_psrc);
    cudaGetSymbolAddress((void**)&p_pdst, g_pdst);

    __nv_bfloat16 *wn_h, *wn_l, *we_h, *we_l;
    __nv_bfloat16 *wc_h, *wc_l, *w1_h, *w1_l, *w2_h, *w2_l;
    __nv_bfloat16 *u1_h, *u1_l, *u2_h, *u2_l, *u3_h, *u3_l;
    __nv_bfloat16 *e2_h, *e2_l, *po_h, *po_l, *li_h, *li_l;
    cudaGetSymbolAddress((void**)&wn_h, g_wn_hi);  cudaGetSymbolAddress((void**)&wn_l, g_wn_lo);
    cudaGetSymbolAddress((void**)&we_h, g_we_hi);  cudaGetSymbolAddress((void**)&we_l, g_we_lo);
    cudaGetSymbolAddress((void**)&wc_h, g_wc_hi);  cudaGetSymbolAddress((void**)&wc_l, g_wc_lo);
    cudaGetSymbolAddress((void**)&w1_h, g_w1_hi);  cudaGetSymbolAddress((void**)&w1_l, g_w1_lo);
    cudaGetSymbolAddress((void**)&w2_h, g_w2_hi);  cudaGetSymbolAddress((void**)&w2_l, g_w2_lo);
    cudaGetSymbolAddress((void**)&u1_h, g_u1_hi);  cudaGetSymbolAddress((void**)&u1_l, g_u1_lo);
    cudaGetSymbolAddress((void**)&u2_h, g_u2_hi);  cudaGetSymbolAddress((void**)&u2_l, g_u2_lo);
    cudaGetSymbolAddress((void**)&u3_h, g_u3_hi);  cudaGetSymbolAddress((void**)&u3_l, g_u3_lo);
    cudaGetSymbolAddress((void**)&e2_h, g_em2_hi); cudaGetSymbolAddress((void**)&e2_l, g_em2_lo);
    cudaGetSymbolAddress((void**)&po_h, g_po_hi);  cudaGetSymbolAddress((void**)&po_l, g_po_lo);
    cudaGetSymbolAddress((void**)&li_h, g_li_hi);  cudaGetSymbolAddress((void**)&li_l, g_li_lo);

    const int SM128 = 2 * 4 * CHB;
    const int SM64  = 2 * 2 * CHB;
    const int SM32  = 2 * 1 * CHB;
    const int SMD   = 4 * 4 * CHB;
    cudaFuncSetAttribute(tcgN<128, 0, false, 1>, cudaFuncAttributeMaxDynamicSharedMemorySize, SM128);
    cudaFuncSetAttribute(tcgN<128, 2, false, 5>, cudaFuncAttributeMaxDynamicSharedMemorySize, SM128);
    cudaFuncSetAttribute(tcgN<128, 3, false, 5>, cudaFuncAttributeMaxDynamicSharedMemorySize, SM128);
    cudaFuncSetAttribute(tcgN<128, 4, false, 5>, cudaFuncAttributeMaxDynamicSharedMemorySize, SM128);
    cudaFuncSetAttribute(tcgN<64, 0, false, 1>,  cudaFuncAttributeMaxDynamicSharedMemorySize, SM64);
    cudaFuncSetAttribute(tcgN<32, 0, false, 1>,  cudaFuncAttributeMaxDynamicSharedMemorySize, SM32);
    cudaFuncSetAttribute(tcgN<32, 0, true, 5>,   cudaFuncAttributeMaxDynamicSharedMemorySize, SM32);
    cudaFuncSetAttribute(tcgN_dual,              cudaFuncAttributeMaxDynamicSharedMemorySize, SMD);

    const int GB_E5 = EE / (128 * 5);      // 625
    const int GB_N  = (NN + 127) / 128;
    const int GB_EP = (EPP + 127) / 128;
    const int G_NH  = (int)(((size_t)NN * HH + 255) / 256);
    const int NBLK  = (NN + 1023) / 1024;

    // ---- CSR build (+ Wedge conversion folded into launch 0) ----
    zero_cnt_we_kernel<<<(NN + 255) / 256, 256>>>(Wedge);
    hist_kernel<<<(EE + 255) / 256, 256>>>(dst);
    scan1_kernel<<<NBLK, 1024>>>();
    scan23_kernel<<<NBLK, 1024>>>();
    scatter_kernel<<<(EE + 255) / 256, 256>>>(src, dst);

    // ---- ea embedding (dst-sorted order via gather, 5 tiles/block) ----
    tcgN<32, 0, true, 5><<<GB_E5, 256, SM32>>>(eattr, p_eord, we_h, we_l, bedge,
        nullptr, nullptr, nullptr, nullptr, p_ea, EE);

    // ---- weight prep ----
    {
        PrepJobs jobs;
        int j = 0;
        jobs.W[j] = Wnode; jobs.hi[j] = wn_h; jobs.lo[j] = wn_l; jobs.K[j] = 64; j++;
        for (int l = 0; l < LLAYERS; l++) {
            const float* preW = pre_w + (size_t)l * 384 * 128;
            const float* em1W = emlp_w1 + (size_t)l * 384 * 128;
            size_t o = (size_t)l * 128 * 128;
            jobs.W[j] = preW;            jobs.hi[j] = w1_h + o; jobs.lo[j] = w1_l + o; jobs.K[j] = 128; j++;
            jobs.W[j] = preW + 128*128;  jobs.hi[j] = w2_h + o; jobs.lo[j] = w2_l + o; jobs.K[j] = 128; j++;
            jobs.W[j] = em1W;            jobs.hi[j] = u1_h + o; jobs.lo[j] = u1_l + o; jobs.K[j] = 128; j++;
            jobs.W[j] = em1W + 128*128;  jobs.hi[j] = u2_h + o; jobs.lo[j] = u2_l + o; jobs.K[j] = 128; j++;
            jobs.W[j] = em1W + 256*128;  jobs.hi[j] = u3_h + o; jobs.lo[j] = u3_l + o; jobs.K[j] = 128; j++;
            jobs.W[j] = emlp_w2 + o;     jobs.hi[j] = e2_h + o; jobs.lo[j] = e2_l + o; jobs.K[j] = 128; j++;
            jobs.W[j] = lin_w + o;       jobs.hi[j] = li_h + o; jobs.lo[j] = li_l + o; jobs.K[j] = 128; j++;
            jobs.W[j] = post_w + (size_t)l * 1664 * 128;
            jobs.hi[j] = po_h + (size_t)l * 128 * 1664;
            jobs.lo[j] = po_l + (size_t)l * 128 * 1664; jobs.K[j] = 1664; j++;
        }
        dim3 grid((1664 * 128 + 255) / 256, NJOBS);
        prep_all_kernel<<<grid, 256>>>(jobs);
    }
    {
        dim3 gwc(64, LLAYERS);
        combine_wc_kernel<<<gwc, 256>>>(eenc_w, pre_w, wc_h, wc_l);
        combine_bc_kernel<<<LLAYERS, 128>>>(eenc_b, pre_w, pre_b, p_bc, p_zero);
    }

    // ---- remaining embeddings ----
    tcgN<64, 0, false, 1><<<GB_N, 256, SM64>>>(x_in, nullptr, wn_h, wn_l, bnode,
        nullptr, nullptr, nullptr, nullptr, p_x, NN);
    tcgN<32, 0, false, 1><<<GB_EP, 256, SM32>>>(pos_attr, nullptr, we_h, we_l, bedge,
        nullptr, nullptr, nullptr, nullptr, outpos, EPP);
    tcgN<32, 0, false, 1><<<GB_EP, 256, SM32>>>(neg_attr, nullptr, we_h, we_l, bedge,
        nullptr, nullptr, nullptr, nullptr, outneg, EPP);

    for (int l = 0; l < LLAYERS; l++) {
        size_t o = (size_t)l * 128 * 128;
        // node partials P1 = x@W1^T + bc, P2 = x@W2^T
        tcgN_dual<<<GB_N, 512, SMD>>>(p_x, w1_h + o, w1_l + o, w2_h + o, w2_l + o,
                                      p_bc + l * 128, p_zero, p_pa, p_pb, NN);
        // h = ea@Wc^T + P1[pdst] + P2[psrc]
        tcgN<128, 3, false, 5><<<GB_E5, 256, SM128>>>(p_ea, nullptr, wc_h + o, wc_l + o, p_zero,
            p_pa, p_pdst, p_pb, p_psrc, p_h, EE);
        // streaming segmented reduce + pin build
        agg_pin_kernel<<<NN, 256>>>(adl);
        // out = (pin@post^T + b) @ lin^T + b
        tcg_big<1664><<<GB_N, 256>>>(p_pin, po_h + (size_t)l * 128 * 1664,
                                     po_l + (size_t)l * 128 * 1664, post_b + l * HH,
                                     p_tmp, NN);
        tcgN<128, 0, false, 1><<<GB_N, 256, SM128>>>(p_tmp, nullptr, li_h + o, li_l + o,
            lin_b + l * HH, nullptr, nullptr, nullptr, nullptr, p_out, NN);
        // batchnorm + residual
        bn_zero_kernel<<<1, 128>>>();
        bn_reduce_kernel<<<GB_N, 128>>>();
        bn_apply_kernel<<<G_NH, 256>>>(bng + l * HH, bnb + l * HH,
                                       (l == LLAYERS - 1) ? outx : nullptr);
        // edge update (separate kernels — chain fusion regressed in R9)
        tcgN_dual<<<GB_N, 512, SMD>>>(p_x, u1_h + o, u1_l + o, u2_h + o, u2_l + o,
                                      emlp_b1 + l * HH, p_zero, p_pa, p_pb, NN);
        tcgN<128, 4, false, 5><<<GB_E5, 256, SM128>>>(p_ea, nullptr, u3_h + o, u3_l + o, p_zero,
            p_pa, p_psrc, p_pb, p_pdst, p_h, EE);
        tcgN<128, 2, false, 5><<<GB_E5, 256, SM128>>>(p_h, nullptr, e2_h + o, e2_l + o,
            emlp_b2 + l * HH, nullptr, nullptr, nullptr, nullptr, p_ea, EE);
    }
}

// round 12
// speedup vs baseline: 1.0405x; 1.0405x over previous
#include <cuda_runtime.h>
#include <cuda_bf16.h>
#include <math.h>
#include <float.h>
#include <stdint.h>

#define NN 50000
#define EE 400000
#define EPP 40000
#define FF 64
#define EDD 32
#define HH 128
#define LLAYERS 2

// ---------------- scratch ----------------
__device__ float g_x   [(size_t)NN*HH];
__device__ float g_ea  [(size_t)EE*HH];
__device__ float g_h   [(size_t)EE*HH];
__device__ float g_pin [(size_t)NN*13*HH];
__device__ float g_out [(size_t)NN*HH];
__device__ float g_pa  [(size_t)NN*HH];
__device__ float g_pb  [(size_t)NN*HH];
__device__ float g_bnsum[HH];
__device__ float g_bnss [HH];
__device__ float g_zerov[HH];
__device__ float g_bc  [LLAYERS*HH];
__device__ float g_bpl [LLAYERS*HH];

// CSR / permutation
__device__ int g_cnt   [NN];
__device__ int g_rowptr[NN + 1];
__device__ int g_wr    [NN];
__device__ int g_eord  [EE];
__device__ int g_psrc  [EE];
__device__ int g_pdst  [EE];
__device__ int g_blksum[64];

// transposed + hi/lo split weights  [N=128][K] bf16
__device__ __nv_bfloat16 g_wn_hi [(size_t)128*64];
__device__ __nv_bfloat16 g_wn_lo [(size_t)128*64];
__device__ __nv_bfloat16 g_we_hi [(size_t)128*32];
__device__ __nv_bfloat16 g_we_lo [(size_t)128*32];
__device__ __nv_bfloat16 g_wc_hi [(size_t)LLAYERS*128*128];
__device__ __nv_bfloat16 g_wc_lo [(size_t)LLAYERS*128*128];
__device__ __nv_bfloat16 g_w1_hi [(size_t)LLAYERS*128*128];
__device__ __nv_bfloat16 g_w1_lo [(size_t)LLAYERS*128*128];
__device__ __nv_bfloat16 g_w2_hi [(size_t)LLAYERS*128*128];
__device__ __nv_bfloat16 g_w2_lo [(size_t)LLAYERS*128*128];
__device__ __nv_bfloat16 g_u1_hi [(size_t)LLAYERS*128*128];
__device__ __nv_bfloat16 g_u1_lo [(size_t)LLAYERS*128*128];
__device__ __nv_bfloat16 g_u2_hi [(size_t)LLAYERS*128*128];
__device__ __nv_bfloat16 g_u2_lo [(size_t)LLAYERS*128*128];
__device__ __nv_bfloat16 g_u3_hi [(size_t)LLAYERS*128*128];
__device__ __nv_bfloat16 g_u3_lo [(size_t)LLAYERS*128*128];
__device__ __nv_bfloat16 g_em2_hi[(size_t)LLAYERS*128*128];
__device__ __nv_bfloat16 g_em2_lo[(size_t)LLAYERS*128*128];
__device__ __nv_bfloat16 g_pl_hi [(size_t)LLAYERS*128*1664];   // post@lin combined
__device__ __nv_bfloat16 g_pl_lo [(size_t)LLAYERS*128*1664];

// ---------------- mma.sync helpers ----------------
__device__ __forceinline__ uint32_t smem_u32(const void* p) {
    uint32_t a;
    asm("{ .reg .u64 t; cvta.to.shared.u64 t, %1; cvt.u32.u64 %0, t; }" : "=r"(a) : "l"(p));
    return a;
}
__device__ __forceinline__ void ldsm4(uint32_t r[4], uint32_t addr) {
    asm volatile("ldmatrix.sync.aligned.m8n8.x4.shared.b16 {%0,%1,%2,%3}, [%4];"
                 : "=r"(r[0]), "=r"(r[1]), "=r"(r[2]), "=r"(r[3]) : "r"(addr));
}
__device__ __forceinline__ void mma16816(float c[4], const uint32_t a[4],
                                         uint32_t b0, uint32_t b1) {
    asm volatile("mma.sync.aligned.m16n8k16.row.col.f32.bf16.bf16.f32 "
                 "{%0,%1,%2,%3}, {%4,%5,%6,%7}, {%8,%9}, {%0,%1,%2,%3};"
                 : "+f"(c[0]), "+f"(c[1]), "+f"(c[2]), "+f"(c[3])
                 : "r"(a[0]), "r"(a[1]), "r"(a[2]), "r"(a[3]), "r"(b0), "r"(b1));
}
// fast hi/lo split: hi = truncate-to-bf16 (PRMT), lo = exact remainder rounded to bf16
__device__ __forceinline__ void cvt2(float2 f, uint32_t& h, uint32_t& l) {
    uint32_t b0 = __float_as_uint(f.x);
    uint32_t b1 = __float_as_uint(f.y);
    h = __byte_perm(b0, b1, 0x7632);
    float l0 = f.x - __uint_as_float(b0 & 0xFFFF0000u);
    float l1 = f.y - __uint_as_float(b1 & 0xFFFF0000u);
    __nv_bfloat162 p = __floats2bfloat162_rn(l0, l1);
    l = *reinterpret_cast<uint32_t*>(&p);
}

#define PITCH 80
#define CHB   10240

// ---------------- sync-free resident-B GEMM (K <= 128) — R8 geometry ----------
template<int K, int EPI, bool GATHER>
__global__ __launch_bounds__(256) void tcgN(
    const float* __restrict__ A, const int* __restrict__ gidx,
    const __nv_bfloat16* __restrict__ Whi, const __nv_bfloat16* __restrict__ Wlo,
    const float* __restrict__ bias,
    const float* __restrict__ G1, const int* __restrict__ idx1,
    const float* __restrict__ G2, const int* __restrict__ idx2,
    float* __restrict__ C, int M)
{
    constexpr int NCH = K / 32;
    constexpr int NST = 2 * NCH;
    extern __shared__ __align__(16) uint8_t sB[];
    uint8_t* sBhi = sB;
    uint8_t* sBlo = sB + NCH * CHB;

    const int tid = threadIdx.x;
    const int wid = tid >> 5;
    const int lid = tid & 31;
    const int m0  = blockIdx.x * 128;

    {
        const int frow = tid >> 1;
        const int fkh  = (tid & 1) * 16;
#pragma unroll
        for (int c = 0; c < NCH; c++) {
            const __nv_bfloat16* sh = Whi + (size_t)frow * K + c * 32 + fkh;
            const __nv_bfloat16* sl = Wlo + (size_t)frow * K + c * 32 + fkh;
            const uint32_t off = c * CHB + frow * PITCH + fkh * 2;
            *(uint4*)(sBhi + off)      = *(const uint4*)sh;
            *(uint4*)(sBhi + off + 16) = *(const uint4*)(sh + 8);
            *(uint4*)(sBlo + off)      = *(const uint4*)sl;
            *(uint4*)(sBlo + off + 16) = *(const uint4*)(sl + 8);
        }
    }
    __syncthreads();

    const int q   = lid >> 2;
    const int c2  = (lid & 3) * 2;
    const int r0g = m0 + wid * 16 + q;
    int ar0 = min(r0g,     M - 1);
    int ar1 = min(r0g + 8, M - 1);
    if (GATHER) { ar0 = gidx[ar0]; ar1 = gidx[ar1]; }
    const float* Arow0 = A + (size_t)ar0 * K;
    const float* Arow1 = A + (size_t)ar1 * K;

    const int r8 = lid & 7, jj = lid >> 3;
    const uint32_t offB = (uint32_t)(((jj >> 1) * 8 + r8) * PITCH + (jj & 1) * 16);
    const uint32_t uBhi = smem_u32(sBhi);
    const uint32_t uBlo = smem_u32(sBlo);

    float acc[16][4];
#pragma unroll
    for (int j = 0; j < 16; j++)
#pragma unroll
        for (int i = 0; i < 4; i++) acc[j][i] = 0.f;

    float2 pf0, pf1, pf2, pf3;
    pf0 = *(const float2*)(Arow0 + c2);
    pf1 = *(const float2*)(Arow1 + c2);
    pf2 = *(const float2*)(Arow0 + c2 + 8);
    pf3 = *(const float2*)(Arow1 + c2 + 8);

#pragma unroll
    for (int step = 0; step < NST; step++) {
        uint32_t ah[4], al[4];
        cvt2(pf0, ah[0], al[0]);
        cvt2(pf1, ah[1], al[1]);
        cvt2(pf2, ah[2], al[2]);
        cvt2(pf3, ah[3], al[3]);
        if (step + 1 < NST) {
            const int k0 = (step + 1) * 16 + c2;
            pf0 = *(const float2*)(Arow0 + k0);
            pf1 = *(const float2*)(Arow1 + k0);
            pf2 = *(const float2*)(Arow0 + k0 + 8);
            pf3 = *(const float2*)(Arow1 + k0 + 8);
        }
        const uint32_t cb  = (uint32_t)(step >> 1) * CHB;
        const uint32_t kso = (uint32_t)(step & 1) * 32;
#pragma unroll
        for (int nb = 0; nb < 8; nb++) {
            uint32_t bh[4], bl[4];
            ldsm4(bh, uBhi + cb + offB + nb * (16 * PITCH) + kso);
            ldsm4(bl, uBlo + cb + offB + nb * (16 * PITCH) + kso);
            mma16816(acc[2 * nb],     ah, bh[0], bh[1]);
            mma16816(acc[2 * nb + 1], ah, bh[2], bh[3]);
            mma16816(acc[2 * nb],     ah, bl[0], bl[1]);
            mma16816(acc[2 * nb + 1], ah, bl[2], bl[3]);
            mma16816(acc[2 * nb],     al, bh[0], bh[1]);
            mma16816(acc[2 * nb + 1], al, bh[2], bh[3]);
        }
    }

#pragma unroll
    for (int h = 0; h < 2; h++) {
        const int r = m0 + wid * 16 + q + h * 8;
        if (r < M) {
            const float* g1 = nullptr;
            const float* g2 = nullptr;
            if (EPI >= 3) {
                g1 = G1 + (size_t)idx1[r] * HH;
                g2 = G2 + (size_t)idx2[r] * HH;
            }
            float* cp = C + (size_t)r * HH;
#pragma unroll
            for (int j = 0; j < 16; j++) {
                const int n0 = j * 8 + c2;
                float v0 = acc[j][h * 2 + 0] + bias[n0];
                float v1 = acc[j][h * 2 + 1] + bias[n0 + 1];
                if (EPI >= 3) {
                    v0 += g1[n0] + g2[n0];
                    v1 += g1[n0 + 1] + g2[n0 + 1];
                }
                if (EPI == 4) { v0 = fmaxf(v0, 0.f); v1 = fmaxf(v1, 0.f); }
                if (EPI == 2) {
                    float2 prev = *(float2*)(cp + n0);
                    v0 = prev.x + 0.5f * v0;
                    v1 = prev.y + 0.5f * v1;
                }
                *(float2*)(cp + n0) = make_float2(v0, v1);
            }
        }
    }
}

// ---------------- dual-output resident-B GEMM (K=128, 512 thr) ----------------
__global__ __launch_bounds__(512) void tcgN_dual(
    const float* __restrict__ A,
    const __nv_bfloat16* __restrict__ W1hi, const __nv_bfloat16* __restrict__ W1lo,
    const __nv_bfloat16* __restrict__ W2hi, const __nv_bfloat16* __restrict__ W2lo,
    const float* __restrict__ b1, const float* __restrict__ b2,
    float* __restrict__ C1, float* __restrict__ C2, int M)
{
    constexpr int K = 128, NCH = 4;
    extern __shared__ __align__(16) uint8_t sB[];
    const int tid = threadIdx.x;
    const int wid = tid >> 5;
    const int lid = tid & 31;
    const int m0  = blockIdx.x * 128;

    {
        const int frow = tid >> 2;
        const int fq   = tid & 3;
        const uint32_t wo = (uint32_t)frow * PITCH + fq * 16;
#pragma unroll
        for (int w = 0; w < 2; w++) {
            const __nv_bfloat16* Whi = w ? W2hi : W1hi;
            const __nv_bfloat16* Wlo = w ? W2lo : W1lo;
            uint8_t* dh = sB + w * (8 * CHB);
            uint8_t* dl = dh + 4 * CHB;
#pragma unroll
            for (int c = 0; c < NCH; c++) {
                const __nv_bfloat16* sh = Whi + (size_t)frow * K + c * 32 + fq * 8;
                const __nv_bfloat16* sl = Wlo + (size_t)frow * K + c * 32 + fq * 8;
                *(uint4*)(dh + c * CHB + wo) = *(const uint4*)sh;
                *(uint4*)(dl + c * CHB + wo) = *(const uint4*)sl;
            }
        }
    }
    __syncthreads();

    const int wsel = wid >> 3;
    const int w8   = wid & 7;
    const int q  = lid >> 2;
    const int c2 = (lid & 3) * 2;
    const int r0g = m0 + w8 * 16 + q;
    const size_t rc0 = (size_t)min(r0g,     M - 1);
    const size_t rc1 = (size_t)min(r0g + 8, M - 1);
    const float* Arow0 = A + rc0 * K;
    const float* Arow1 = A + rc1 * K;

    const int r8 = lid & 7, jj = lid >> 3;
    const uint32_t offB = (uint32_t)(((jj >> 1) * 8 + r8) * PITCH + (jj & 1) * 16);
    const uint32_t uBhi = smem_u32(sB) + wsel * (8 * CHB);
    const uint32_t uBlo = uBhi + 4 * CHB;

    float acc[16][4];
#pragma unroll
    for (int j = 0; j < 16; j++)
#pragma unroll
        for (int i = 0; i < 4; i++) acc[j][i] = 0.f;

    float2 pf0, pf1, pf2, pf3;
    pf0 = *(const float2*)(Arow0 + c2);
    pf1 = *(const float2*)(Arow1 + c2);
    pf2 = *(const float2*)(Arow0 + c2 + 8);
    pf3 = *(const float2*)(Arow1 + c2 + 8);
#pragma unroll
    for (int step = 0; step < 8; step++) {
        uint32_t ah[4], al[4];
        cvt2(pf0, ah[0], al[0]);
        cvt2(pf1, ah[1], al[1]);
        cvt2(pf2, ah[2], al[2]);
        cvt2(pf3, ah[3], al[3]);
        if (step + 1 < 8) {
            const int k0 = (step + 1) * 16 + c2;
            pf0 = *(const float2*)(Arow0 + k0);
            pf1 = *(const float2*)(Arow1 + k0);
            pf2 = *(const float2*)(Arow0 + k0 + 8);
            pf3 = *(const float2*)(Arow1 + k0 + 8);
        }
        const uint32_t cb  = (uint32_t)(step >> 1) * CHB;
        const uint32_t kso = (uint32_t)(step & 1) * 32;
#pragma unroll
        for (int nb = 0; nb < 8; nb++) {
            uint32_t bh[4], bl[4];
            ldsm4(bh, uBhi + cb + offB + nb * (16 * PITCH) + kso);
            ldsm4(bl, uBlo + cb + offB + nb * (16 * PITCH) + kso);
            mma16816(acc[2 * nb],     ah, bh[0], bh[1]);
            mma16816(acc[2 * nb + 1], ah, bh[2], bh[3]);
            mma16816(acc[2 * nb],     ah, bl[0], bl[1]);
            mma16816(acc[2 * nb + 1], ah, bl[2], bl[3]);
            mma16816(acc[2 * nb],     al, bh[0], bh[1]);
            mma16816(acc[2 * nb + 1], al, bh[2], bh[3]);
        }
    }

    const float* bias = wsel ? b2 : b1;
    float* C = wsel ? C2 : C1;
#pragma unroll
    for (int h = 0; h < 2; h++) {
        const int r = m0 + w8 * 16 + q + h * 8;
        if (r < M) {
            float* cp = C + (size_t)r * HH;
#pragma unroll
            for (int j = 0; j < 16; j++) {
                const int n0 = j * 8 + c2;
                *(float2*)(cp + n0) = make_float2(acc[j][h * 2 + 0] + bias[n0],
                                                  acc[j][h * 2 + 1] + bias[n0 + 1]);
            }
        }
    }
}

// ---------------- chunked pipeline GEMM (K=1664: post@lin combined) ----------------
template<int K>
__global__ __launch_bounds__(256) void tcg_big(
    const float* __restrict__ A,
    const __nv_bfloat16* __restrict__ Whi, const __nv_bfloat16* __restrict__ Wlo,
    const float* __restrict__ bias, float* __restrict__ C, int M)
{
    __shared__ __align__(16) uint8_t sAhi[128 * PITCH];
    __shared__ __align__(16) uint8_t sAlo[128 * PITCH];
    __shared__ __align__(16) uint8_t sBhi[128 * PITCH];
    __shared__ __align__(16) uint8_t sBlo[128 * PITCH];

    const int tid = threadIdx.x;
    const int wid = tid >> 5;
    const int lid = tid & 31;
    const int m0  = blockIdx.x * 128;

    const int frow = tid >> 1;
    const int fkh  = (tid & 1) * 16;
    const int ar   = min(m0 + frow, M - 1);
    const float* aRow = A + (size_t)ar * K;
    const __nv_bfloat16* bhRow = Whi + (size_t)frow * K;
    const __nv_bfloat16* blRow = Wlo + (size_t)frow * K;
    uint8_t* aHiDst = sAhi + frow * PITCH + fkh * 2;
    uint8_t* aLoDst = sAlo + frow * PITCH + fkh * 2;
    uint8_t* bHiDst = sBhi + frow * PITCH + fkh * 2;
    uint8_t* bLoDst = sBlo + frow * PITCH + fkh * 2;

    const int r8 = lid & 7, jj = lid >> 3;
    const uint32_t offA = (uint32_t)(((jj & 1) * 8 + r8 + wid * 16) * PITCH + (jj >> 1) * 16);
    const uint32_t offB = (uint32_t)(((jj >> 1) * 8 + r8) * PITCH + (jj & 1) * 16);
    const uint32_t uAhi = smem_u32(sAhi), uAlo = smem_u32(sAlo);
    const uint32_t uBhi = smem_u32(sBhi), uBlo = smem_u32(sBlo);

    float acc[16][4];
#pragma unroll
    for (int j = 0; j < 16; j++)
#pragma unroll
        for (int i = 0; i < 4; i++) acc[j][i] = 0.f;

    for (int kc = 0; kc < K; kc += 32) {
        float4 f0 = *(const float4*)(aRow + kc + fkh + 0);
        float4 f1 = *(const float4*)(aRow + kc + fkh + 4);
        float4 f2 = *(const float4*)(aRow + kc + fkh + 8);
        float4 f3 = *(const float4*)(aRow + kc + fkh + 12);
        uint4 bh0 = *(const uint4*)(bhRow + kc + fkh);
        uint4 bh1 = *(const uint4*)(bhRow + kc + fkh + 8);
        uint4 bl0 = *(const uint4*)(blRow + kc + fkh);
        uint4 bl1 = *(const uint4*)(blRow + kc + fkh + 8);

        float f[16] = {f0.x, f0.y, f0.z, f0.w, f1.x, f1.y, f1.z, f1.w,
                       f2.x, f2.y, f2.z, f2.w, f3.x, f3.y, f3.z, f3.w};
        uint32_t hw[8], lw[8];
#pragma unroll
        for (int i = 0; i < 8; i++) {
            float2 p = make_float2(f[2 * i], f[2 * i + 1]);
            cvt2(p, hw[i], lw[i]);
        }

        __syncthreads();
        *(uint4*)(aHiDst)      = make_uint4(hw[0], hw[1], hw[2], hw[3]);
        *(uint4*)(aHiDst + 16) = make_uint4(hw[4], hw[5], hw[6], hw[7]);
        *(uint4*)(aLoDst)      = make_uint4(lw[0], lw[1], lw[2], lw[3]);
        *(uint4*)(aLoDst + 16) = make_uint4(lw[4], lw[5], lw[6], lw[7]);
        *(uint4*)(bHiDst)      = bh0;
        *(uint4*)(bHiDst + 16) = bh1;
        *(uint4*)(bLoDst)      = bl0;
        *(uint4*)(bLoDst + 16) = bl1;
        __syncthreads();

#pragma unroll
        for (int ks = 0; ks < 2; ks++) {
            const uint32_t kso = ks * 32;
            uint32_t ah[4], al[4];
            ldsm4(ah, uAhi + offA + kso);
            ldsm4(al, uAlo + offA + kso);
#pragma unroll
            for (int nb = 0; nb < 8; nb++) {
                uint32_t bh[4], bl[4];
                ldsm4(bh, uBhi + offB + nb * (16 * PITCH) + kso);
                ldsm4(bl, uBlo + offB + nb * (16 * PITCH) + kso);
                mma16816(acc[2 * nb],     ah, bh[0], bh[1]);
                mma16816(acc[2 * nb + 1], ah, bh[2], bh[3]);
                mma16816(acc[2 * nb],     ah, bl[0], bl[1]);
                mma16816(acc[2 * nb + 1], ah, bl[2], bl[3]);
                mma16816(acc[2 * nb],     al, bh[0], bh[1]);
                mma16816(acc[2 * nb + 1], al, bh[2], bh[3]);
            }
        }
    }

    const int q  = lid >> 2;
    const int c2 = (lid & 3) * 2;
#pragma unroll
    for (int h = 0; h < 2; h++) {
        const int r = m0 + wid * 16 + q + h * 8;
        if (r < M) {
            float* cp = C + (size_t)r * HH;
#pragma unroll
            for (int j = 0; j < 16; j++) {
                const int n0 = j * 8 + c2;
                *(float2*)(cp + n0) = make_float2(acc[j][h * 2 + 0] + bias[n0],
                                                  acc[j][h * 2 + 1] + bias[n0 + 1]);
            }
        }
    }
}

// ---------------- batched weight prep (13 jobs; post/lin replaced by combine) ----
#define NJOBS 13
struct PrepJobs {
    const float* W[NJOBS];
    __nv_bfloat16* hi[NJOBS];
    __nv_bfloat16* lo[NJOBS];
    int K[NJOBS];
};
__global__ void prep_all_kernel(PrepJobs jobs) {
    const int job = blockIdx.y;
    const int K = jobs.K[job];
    const int i = blockIdx.x * 256 + threadIdx.x;
    if (i >= K * 128) return;
    const int k = i >> 7, n = i & 127;
    float w = jobs.W[job][i];
    __nv_bfloat16 h = __float2bfloat16(w);
    float rem = w - __bfloat162float(h);
    jobs.hi[job][(size_t)n * K + k] = h;
    jobs.lo[job][(size_t)n * K + k] = __float2bfloat16(rem);
}

__global__ void combine_wc_kernel(const float* __restrict__ eenc_w,
                                  const float* __restrict__ pre_w,
                                  __nv_bfloat16* __restrict__ hi,
                                  __nv_bfloat16* __restrict__ lo) {
    const int l = blockIdx.y;
    const float* ew = eenc_w + (size_t)l * 128 * 128;
    const float* W3 = pre_w + (size_t)l * 384 * 128 + 256 * 128;
    int i = blockIdx.x * blockDim.x + threadIdx.x;
    int k = i >> 7, n = i & 127;
    float s = 0.f;
    for (int j = 0; j < 128; j++) s += ew[k * 128 + j] * W3[j * 128 + n];
    __nv_bfloat16 h = __float2bfloat16(s);
    float rem = s - __bfloat162float(h);
    size_t o = (size_t)l * 128 * 128;
    hi[o + (size_t)n * 128 + k] = h;
    lo[o + (size_t)n * 128 + k] = __float2bfloat16(rem);
}
__global__ void combine_bc_kernel(const float* __restrict__ eenc_b,
                                  const float* __restrict__ pre_w,
                                  const float* __restrict__ pre_b,
                                  float* __restrict__ bc, float* __restrict__ zv) {
    const int l = blockIdx.x;
    const float* W3 = pre_w + (size_t)l * 384 * 128 + 256 * 128;
    int n = threadIdx.x;
    float s = pre_b[l * 128 + n];
    for (int j = 0; j < 128; j++) s += eenc_b[l * 128 + j] * W3[j * 128 + n];
    bc[l * 128 + n] = s;
    if (l == 0) zv[n] = 0.f;
}

// W_pl[k][n] = sum_j post_w[k][j] * lin_w[j][n]   (K=1664), output transposed+split
__global__ void combine_pl_kernel(const float* __restrict__ post_w,
                                  const float* __restrict__ lin_w,
                                  __nv_bfloat16* __restrict__ hi,
                                  __nv_bfloat16* __restrict__ lo) {
    const int l = blockIdx.y;
    const float* pw = post_w + (size_t)l * 1664 * 128;
    const float* lw = lin_w + (size_t)l * 128 * 128;
    int i = blockIdx.x * blockDim.x + threadIdx.x;
    if (i >= 1664 * 128) return;
    int k = i >> 7, n = i & 127;
    float s = 0.f;
    for (int j = 0; j < 128; j++) s += pw[(size_t)k * 128 + j] * lw[j * 128 + n];
    __nv_bfloat16 h = __float2bfloat16(s);
    float rem = s - __bfloat162float(h);
    size_t o = (size_t)l * 128 * 1664;
    hi[o + (size_t)n * 1664 + k] = h;
    lo[o + (size_t)n * 1664 + k] = __float2bfloat16(rem);
}
// b_pl[n] = post_b @ lin_w + lin_b
__global__ void combine_bpl_kernel(const float* __restrict__ post_b,
                                   const float* __restrict__ lin_w,
                                   const float* __restrict__ lin_b,
                                   float* __restrict__ bpl) {
    const int l = blockIdx.x;
    const float* lw = lin_w + (size_t)l * 128 * 128;
    int n = threadIdx.x;
    float s = lin_b[l * 128 + n];
    for (int j = 0; j < 128; j++) s += post_b[l * 128 + j] * lw[j * 128 + n];
    bpl[l * 128 + n] = s;
}

// ---------------- CSR build + edge permutation ----------------
__global__ void zero_cnt_we_kernel(const float* __restrict__ We) {
    int i = blockIdx.x * blockDim.x + threadIdx.x;
    if (i < NN) g_cnt[i] = 0;
    if (i < EDD * 128) {
        int k = i >> 7, n = i & 127;
        float w = We[i];
        __nv_bfloat16 h = __float2bfloat16(w);
        float rem = w - __bfloat162float(h);
        g_we_hi[(size_t)n * EDD + k] = h;
        g_we_lo[(size_t)n * EDD + k] = __float2bfloat16(rem);
    }
}
__global__ void hist_kernel(const int* __restrict__ dst) {
    int e = blockIdx.x * blockDim.x + threadIdx.x;
    if (e < EE) atomicAdd(&g_cnt[dst[e]], 1);
}
__global__ void scan1_kernel() {
    __shared__ int s[1024];
    int t = threadIdx.x, i = blockIdx.x * 1024 + t;
    int v = (i < NN) ? g_cnt[i] : 0;
    s[t] = v;
    __syncthreads();
    for (int off = 1; off < 1024; off <<= 1) {
        int y = (t >= off) ? s[t - off] : 0;
        __syncthreads();
        s[t] += y;
        __syncthreads();
    }
    if (i < NN) g_rowptr[i] = s[t] - v;
    if (t == 1023) g_blksum[blockIdx.x] = s[1023];
}
__global__ void scan23_kernel() {
    __shared__ int base;
    if (threadIdx.x == 0) {
        int run = 0;
        for (int b = 0; b < (int)blockIdx.x; b++) run += g_blksum[b];
        base = run;
    }
    __syncthreads();
    int i = blockIdx.x * 1024 + threadIdx.x;
    if (i < NN) {
        int r = g_rowptr[i] + base;
        g_rowptr[i] = r;
        g_wr[i] = r;
    }
    if (i == 0) g_rowptr[NN] = EE;
}
__global__ void scatter_kernel(const int* __restrict__ src, const int* __restrict__ dst) {
    int e = blockIdx.x * blockDim.x + threadIdx.x;
    if (e < EE) {
        int d = dst[e];
        int o = atomicAdd(&g_wr[d], 1);
        g_eord[o] = e;
        g_psrc[o] = src[e];
        g_pdst[o] = d;
    }
}

// ---------------- fused streaming segmented reduce + pin build (R8 form) --------
__global__ void agg_pin_kernel(const float* __restrict__ adl_ptr) {
    const int n = blockIdx.x;
    const int c = threadIdx.x;
    const int a = g_rowptr[n], b = g_rowptr[n + 1];
    float sum = 0.f, ss = 0.f, mn = FLT_MAX, mx = -FLT_MAX;
    for (int i = a; i < b; i++) {
        float v = g_h[(size_t)i * HH + c];
        sum += v;
        ss  += v * v;
        mn = fminf(mn, v);
        mx = fmaxf(mx, v);
    }
    float deg  = (float)(b - a);
    float degc = fmaxf(deg, 1.f);
    float adl  = *adl_ptr;
    float logd = logf(degc + 1.f);
    float amp  = logd / adl;
    float att  = adl / logd;
    if (deg <= 0.f) { mn = 0.f; mx = 0.f; }
    float mean = sum / degc;
    float var  = ss / degc - mean * mean;
    float stdv = sqrtf(fmaxf(var, 0.f) + 1e-5f);
    float* r = g_pin + (size_t)n * (13 * HH);
    r[0 * HH + c]  = g_x[(size_t)n * HH + c];
    r[1 * HH + c]  = mean;
    r[2 * HH + c]  = mn;
    r[3 * HH + c]  = mx;
    r[4 * HH + c]  = stdv;
    r[5 * HH + c]  = mean * amp;
    r[6 * HH + c]  = mn * amp;
    r[7 * HH + c]  = mx * amp;
    r[8 * HH + c]  = stdv * amp;
    r[9 * HH + c]  = mean * att;
    r[10 * HH + c] = mn * att;
    r[11 * HH + c] = mx * att;
    r[12 * HH + c] = stdv * att;
}

// ---------------- batchnorm + residual ----------------
__global__ void bn_zero_kernel() {
    if (threadIdx.x < HH) { g_bnsum[threadIdx.x] = 0.f; g_bnss[threadIdx.x] = 0.f; }
}
__global__ void bn_reduce_kernel() {
    int c  = threadIdx.x;
    int r0 = blockIdx.x * 128;
    int r1 = min(r0 + 128, NN);
    float s = 0.f, ss = 0.f;
    for (int r = r0; r < r1; r++) {
        float v = g_out[(size_t)r * HH + c];
        s += v; ss += v * v;
    }
    atomicAdd(&g_bnsum[c], s);
    atomicAdd(&g_bnss[c], ss);
}
__global__ void bn_apply_kernel(const float* __restrict__ gamma,
                                const float* __restrict__ beta,
                                float* __restrict__ xout) {
    size_t idx = (size_t)blockIdx.x * blockDim.x + threadIdx.x;
    if (idx >= (size_t)NN * HH) return;
    int c = (int)(idx & 127);
    float mu  = g_bnsum[c] / (float)NN;
    float var = g_bnss[c] / (float)NN - mu * mu;
    float v = gamma[c] * (g_out[idx] - mu) * rsqrtf(var + 1e-5f) + beta[c];
    float r = (g_x[idx] + fmaxf(v, 0.f)) * 0.5f;
    g_x[idx] = r;
    if (xout) xout[idx] = r;
}

// ---------------- launch ----------------
extern "C" void kernel_launch(void* const* d_in, const int* in_sizes, int n_in,
                              void* d_out, int out_size) {
    (void)in_sizes; (void)n_in; (void)out_size;

    const float* x_in     = (const float*)d_in[0];
    const int*   ei       = (const int*)  d_in[1];
    const float* eattr    = (const float*)d_in[2];
    const float* pos_attr = (const float*)d_in[4];
    const float* neg_attr = (const float*)d_in[6];
    const float* adl      = (const float*)d_in[7];
    const float* Wnode    = (const float*)d_in[8];
    const float* bnode    = (const float*)d_in[9];
    const float* Wedge    = (const float*)d_in[10];
    const float* bedge    = (const float*)d_in[11];
    const float* eenc_w   = (const float*)d_in[12];
    const float* eenc_b   = (const float*)d_in[13];
    const float* pre_w    = (const float*)d_in[14];
    const float* pre_b    = (const float*)d_in[15];
    const float* post_w   = (const float*)d_in[16];
    const float* post_b   = (const float*)d_in[17];
    const float* lin_w    = (const float*)d_in[18];
    const float* lin_b    = (const float*)d_in[19];
    const float* emlp_w1  = (const float*)d_in[20];
    const float* emlp_b1  = (const float*)d_in[21];
    const float* emlp_w2  = (const float*)d_in[22];
    const float* emlp_b2  = (const float*)d_in[23];
    const float* bng      = (const float*)d_in[24];
    const float* bnb      = (const float*)d_in[25];

    const int* src = ei;
    const int* dst = ei + EE;

    float* outx   = (float*)d_out;
    float* outpos = outx + (size_t)NN * HH;
    float* outneg = outpos + (size_t)EPP * HH;

    float *p_x, *p_ea, *p_h, *p_pin, *p_out, *p_pa, *p_pb, *p_zero, *p_bc, *p_bpl;
    cudaGetSymbolAddress((void**)&p_x,    g_x);
    cudaGetSymbolAddress((void**)&p_ea,   g_ea);
    cudaGetSymbolAddress((void**)&p_h,    g_h);
    cudaGetSymbolAddress((void**)&p_pin,  g_pin);
    cudaGetSymbolAddress((void**)&p_out,  g_out);
    cudaGetSymbolAddress((void**)&p_pa,   g_pa);
    cudaGetSymbolAddress((void**)&p_pb,   g_pb);
    cudaGetSymbolAddress((void**)&p_zero, g_zerov);
    cudaGetSymbolAddress((void**)&p_bc,   g_bc);
    cudaGetSymbolAddress((void**)&p_bpl,  g_bpl);

    int *p_eord, *p_psrc, *p_pdst;
    cudaGetSymbolAddress((void**)&p_eord, g_eord);
    cudaGetSymbolAddress((void**)&p_psrc, g_psrc);
    cudaGetSymbolAddress((void**)&p_pdst, g_pdst);

    __nv_bfloat16 *wn_h, *wn_l, *we_h, *we_l;
    __nv_bfloat16 *wc_h, *wc_l, *w1_h, *w1_l, *w2_h, *w2_l;
    __nv_bfloat16 *u1_h, *u1_l, *u2_h, *u2_l, *u3_h, *u3_l;
    __nv_bfloat16 *e2_h, *e2_l, *pl_h, *pl_l;
    cudaGetSymbolAddress((void**)&wn_h, g_wn_hi);  cudaGetSymbolAddress((void**)&wn_l, g_wn_lo);
    cudaGetSymbolAddress((void**)&we_h, g_we_hi);  cudaGetSymbolAddress((void**)&we_l, g_we_lo);
    cudaGetSymbolAddress((void**)&wc_h, g_wc_hi);  cudaGetSymbolAddress((void**)&wc_l, g_wc_lo);
    cudaGetSymbolAddress((void**)&w1_h, g_w1_hi);  cudaGetSymbolAddress((void**)&w1_l, g_w1_lo);
    cudaGetSymbolAddress((void**)&w2_h, g_w2_hi);  cudaGetSymbolAddress((void**)&w2_l, g_w2_lo);
    cudaGetSymbolAddress((void**)&u1_h, g_u1_hi);  cudaGetSymbolAddress((void**)&u1_l, g_u1_lo);
    cudaGetSymbolAddress((void**)&u2_h, g_u2_hi);  cudaGetSymbolAddress((void**)&u2_l, g_u2_lo);
    cudaGetSymbolAddress((void**)&u3_h, g_u3_hi);  cudaGetSymbolAddress((void**)&u3_l, g_u3_lo);
    cudaGetSymbolAddress((void**)&e2_h, g_em2_hi); cudaGetSymbolAddress((void**)&e2_l, g_em2_lo);
    cudaGetSymbolAddress((void**)&pl_h, g_pl_hi);  cudaGetSymbolAddress((void**)&pl_l, g_pl_lo);

    const int SM128 = 2 * 4 * CHB;
    const int SM64  = 2 * 2 * CHB;
    const int SM32  = 2 * 1 * CHB;
    const int SMD   = 4 * 4 * CHB;
    cudaFuncSetAttribute(tcgN<128, 2, false>, cudaFuncAttributeMaxDynamicSharedMemorySize, SM128);
    cudaFuncSetAttribute(tcgN<128, 3, false>, cudaFuncAttributeMaxDynamicSharedMemorySize, SM128);
    cudaFuncSetAttribute(tcgN<128, 4, false>, cudaFuncAttributeMaxDynamicSharedMemorySize, SM128);
    cudaFuncSetAttribute(tcgN<64, 0, false>,  cudaFuncAttributeMaxDynamicSharedMemorySize, SM64);
    cudaFuncSetAttribute(tcgN<32, 0, false>,  cudaFuncAttributeMaxDynamicSharedMemorySize, SM32);
    cudaFuncSetAttribute(tcgN<32, 0, true>,   cudaFuncAttributeMaxDynamicSharedMemorySize, SM32);
    cudaFuncSetAttribute(tcgN_dual,           cudaFuncAttributeMaxDynamicSharedMemorySize, SMD);

    const int GB_E  = EE / 128;            // 3125
    const int GB_N  = (NN + 127) / 128;
    const int GB_EP = (EPP + 127) / 128;
    const int G_NH  = (int)(((size_t)NN * HH + 255) / 256);
    const int NBLK  = (NN + 1023) / 1024;

    // ---- CSR build (+ Wedge conversion folded into launch 0) ----
    zero_cnt_we_kernel<<<(NN + 255) / 256, 256>>>(Wedge);
    hist_kernel<<<(EE + 255) / 256, 256>>>(dst);
    scan1_kernel<<<NBLK, 1024>>>();
    scan23_kernel<<<NBLK, 1024>>>();
    scatter_kernel<<<(EE + 255) / 256, 256>>>(src, dst);

    // ---- ea embedding (dst-sorted order via gather) ----
    tcgN<32, 0, true><<<GB_E, 256, SM32>>>(eattr, p_eord, we_h, we_l, bedge,
        nullptr, nullptr, nullptr, nullptr, p_ea, EE);

    // ---- weight prep ----
    {
        PrepJobs jobs;
        int j = 0;
        jobs.W[j] = Wnode; jobs.hi[j] = wn_h; jobs.lo[j] = wn_l; jobs.K[j] = 64; j++;
        for (int l = 0; l < LLAYERS; l++) {
            const float* preW = pre_w + (size_t)l * 384 * 128;
            const float* em1W = emlp_w1 + (size_t)l * 384 * 128;
            size_t o = (size_t)l * 128 * 128;
            jobs.W[j] = preW;            jobs.hi[j] = w1_h + o; jobs.lo[j] = w1_l + o; jobs.K[j] = 128; j++;
            jobs.W[j] = preW + 128*128;  jobs.hi[j] = w2_h + o; jobs.lo[j] = w2_l + o; jobs.K[j] = 128; j++;
            jobs.W[j] = em1W;            jobs.hi[j] = u1_h + o; jobs.lo[j] = u1_l + o; jobs.K[j] = 128; j++;
            jobs.W[j] = em1W + 128*128;  jobs.hi[j] = u2_h + o; jobs.lo[j] = u2_l + o; jobs.K[j] = 128; j++;
            jobs.W[j] = em1W + 256*128;  jobs.hi[j] = u3_h + o; jobs.lo[j] = u3_l + o; jobs.K[j] = 128; j++;
            jobs.W[j] = emlp_w2 + o;     jobs.hi[j] = e2_h + o; jobs.lo[j] = e2_l + o; jobs.K[j] = 128; j++;
        }
        dim3 grid((128 * 128 + 255) / 256, NJOBS);
        prep_all_kernel<<<grid, 256>>>(jobs);
    }
    {
        dim3 gwc(64, LLAYERS);
        combine_wc_kernel<<<gwc, 256>>>(eenc_w, pre_w, wc_h, wc_l);
        combine_bc_kernel<<<LLAYERS, 128>>>(eenc_b, pre_w, pre_b, p_bc, p_zero);
        dim3 gpl((1664 * 128 + 255) / 256, LLAYERS);
        combine_pl_kernel<<<gpl, 256>>>(post_w, lin_w, pl_h, pl_l);
        combine_bpl_kernel<<<LLAYERS, 128>>>(post_b, lin_w, lin_b, p_bpl);
    }

    // ---- remaining embeddings ----
    tcgN<64, 0, false><<<GB_N, 256, SM64>>>(x_in, nullptr, wn_h, wn_l, bnode,
        nullptr, nullptr, nullptr, nullptr, p_x, NN);
    tcgN<32, 0, false><<<GB_EP, 256, SM32>>>(pos_attr, nullptr, we_h, we_l, bedge,
        nullptr, nullptr, nullptr, nullptr, outpos, EPP);
    tcgN<32, 0, false><<<GB_EP, 256, SM32>>>(neg_attr, nullptr, we_h, we_l, bedge,
        nullptr, nullptr, nullptr, nullptr, outneg, EPP);

    for (int l = 0; l < LLAYERS; l++) {
        size_t o = (size_t)l * 128 * 128;
        // node partials P1 = x@W1^T + bc, P2 = x@W2^T
        tcgN_dual<<<GB_N, 512, SMD>>>(p_x, w1_h + o, w1_l + o, w2_h + o, w2_l + o,
                                      p_bc + l * 128, p_zero, p_pa, p_pb, NN);
        // h = ea@Wc^T + P1[pdst] + P2[psrc]
        tcgN<128, 3, false><<<GB_E, 256, SM128>>>(p_ea, nullptr, wc_h + o, wc_l + o, p_zero,
            p_pa, p_pdst, p_pb, p_psrc, p_h, EE);
        // streaming segmented reduce + pin build
        agg_pin_kernel<<<NN, 128>>>(adl);
        // out = pin@(post@lin)^T + b_pl   (lin folded away)
        tcg_big<1664><<<GB_N, 256>>>(p_pin, pl_h + (size_t)l * 128 * 1664,
                                     pl_l + (size_t)l * 128 * 1664, p_bpl + l * HH,
                                     p_out, NN);
        // batchnorm + residual
        bn_zero_kernel<<<1, 128>>>();
        bn_reduce_kernel<<<GB_N, 128>>>();
        bn_apply_kernel<<<G_NH, 256>>>(bng + l * HH, bnb + l * HH,
                                       (l == LLAYERS - 1) ? outx : nullptr);
        // edge update
        tcgN_dual<<<GB_N, 512, SMD>>>(p_x, u1_h + o, u1_l + o, u2_h + o, u2_l + o,
                                      emlp_b1 + l * HH, p_zero, p_pa, p_pb, NN);
        tcgN<128, 4, false><<<GB_E, 256, SM128>>>(p_ea, nullptr, u3_h + o, u3_l + o, p_zero,
            p_pa, p_psrc, p_pb, p_pdst, p_h, EE);
        tcgN<128, 2, false><<<GB_E, 256, SM128>>>(p_h, nullptr, e2_h + o, e2_l + o,
            emlp_b2 + l * HH, nullptr, nullptr, nullptr, nullptr, p_ea, EE);
    }
}

// round 13
// speedup vs baseline: 1.0712x; 1.0294x over previous
#include <cuda_runtime.h>
#include <cuda_bf16.h>
#include <math.h>
#include <float.h>
#include <stdint.h>

#define NN 50000
#define EE 400000
#define EPP 40000
#define FF 64
#define EDD 32
#define HH 128
#define LLAYERS 2

// ---------------- scratch ----------------
__device__ float g_x   [(size_t)NN*HH];
__device__ float g_ea  [(size_t)EE*HH];
__device__ float g_h   [(size_t)EE*HH];
__device__ float g_agg [(size_t)NN*4*HH];   // [mean|mn|mx|std] per node
__device__ float2 g_scale[NN];              // (amp, att) per node
__device__ float g_out [(size_t)NN*HH];
__device__ float g_pa  [(size_t)NN*HH];
__device__ float g_pb  [(size_t)NN*HH];
__device__ float g_bnsum[HH];
__device__ float g_bnss [HH];
__device__ float g_zerov[HH];
__device__ float g_bc  [LLAYERS*HH];
__device__ float g_bpl [LLAYERS*HH];

// CSR / permutation
__device__ int g_cnt   [NN];
__device__ int g_rowptr[NN + 1];
__device__ int g_wr    [NN];
__device__ int g_eord  [EE];
__device__ int g_psrc  [EE];
__device__ int g_pdst  [EE];
__device__ int g_blksum[64];

// transposed + hi/lo split weights  [N=128][K] bf16
__device__ __nv_bfloat16 g_wn_hi [(size_t)128*64];
__device__ __nv_bfloat16 g_wn_lo [(size_t)128*64];
__device__ __nv_bfloat16 g_we_hi [(size_t)128*32];
__device__ __nv_bfloat16 g_we_lo [(size_t)128*32];
__device__ __nv_bfloat16 g_wc_hi [(size_t)LLAYERS*128*128];
__device__ __nv_bfloat16 g_wc_lo [(size_t)LLAYERS*128*128];
__device__ __nv_bfloat16 g_w1_hi [(size_t)LLAYERS*128*128];
__device__ __nv_bfloat16 g_w1_lo [(size_t)LLAYERS*128*128];
__device__ __nv_bfloat16 g_w2_hi [(size_t)LLAYERS*128*128];
__device__ __nv_bfloat16 g_w2_lo [(size_t)LLAYERS*128*128];
__device__ __nv_bfloat16 g_u1_hi [(size_t)LLAYERS*128*128];
__device__ __nv_bfloat16 g_u1_lo [(size_t)LLAYERS*128*128];
__device__ __nv_bfloat16 g_u2_hi [(size_t)LLAYERS*128*128];
__device__ __nv_bfloat16 g_u2_lo [(size_t)LLAYERS*128*128];
__device__ __nv_bfloat16 g_u3_hi [(size_t)LLAYERS*128*128];
__device__ __nv_bfloat16 g_u3_lo [(size_t)LLAYERS*128*128];
__device__ __nv_bfloat16 g_em2_hi[(size_t)LLAYERS*128*128];
__device__ __nv_bfloat16 g_em2_lo[(size_t)LLAYERS*128*128];
__device__ __nv_bfloat16 g_pl_hi [(size_t)LLAYERS*128*1664];   // post@lin combined
__device__ __nv_bfloat16 g_pl_lo [(size_t)LLAYERS*128*1664];

// ---------------- mma.sync helpers ----------------
__device__ __forceinline__ uint32_t smem_u32(const void* p) {
    uint32_t a;
    asm("{ .reg .u64 t; cvta.to.shared.u64 t, %1; cvt.u32.u64 %0, t; }" : "=r"(a) : "l"(p));
    return a;
}
__device__ __forceinline__ void ldsm4(uint32_t r[4], uint32_t addr) {
    asm volatile("ldmatrix.sync.aligned.m8n8.x4.shared.b16 {%0,%1,%2,%3}, [%4];"
                 : "=r"(r[0]), "=r"(r[1]), "=r"(r[2]), "=r"(r[3]) : "r"(addr));
}
__device__ __forceinline__ void mma16816(float c[4], const uint32_t a[4],
                                         uint32_t b0, uint32_t b1) {
    asm volatile("mma.sync.aligned.m16n8k16.row.col.f32.bf16.bf16.f32 "
                 "{%0,%1,%2,%3}, {%4,%5,%6,%7}, {%8,%9}, {%0,%1,%2,%3};"
                 : "+f"(c[0]), "+f"(c[1]), "+f"(c[2]), "+f"(c[3])
                 : "r"(a[0]), "r"(a[1]), "r"(a[2]), "r"(a[3]), "r"(b0), "r"(b1));
}
// fast hi/lo split: hi = truncate-to-bf16 (PRMT), lo = exact remainder rounded to bf16
__device__ __forceinline__ void cvt2(float2 f, uint32_t& h, uint32_t& l) {
    uint32_t b0 = __float_as_uint(f.x);
    uint32_t b1 = __float_as_uint(f.y);
    h = __byte_perm(b0, b1, 0x7632);
    float l0 = f.x - __uint_as_float(b0 & 0xFFFF0000u);
    float l1 = f.y - __uint_as_float(b1 & 0xFFFF0000u);
    __nv_bfloat162 p = __floats2bfloat162_rn(l0, l1);
    l = *reinterpret_cast<uint32_t*>(&p);
}

#define PITCH 80
#define CHB   10240

// ---------------- sync-free resident-B GEMM (K <= 128) ----------------
template<int K, int EPI, bool GATHER>
__global__ __launch_bounds__(256) void tcgN(
    const float* __restrict__ A, const int* __restrict__ gidx,
    const __nv_bfloat16* __restrict__ Whi, const __nv_bfloat16* __restrict__ Wlo,
    const float* __restrict__ bias,
    const float* __restrict__ G1, const int* __restrict__ idx1,
    const float* __restrict__ G2, const int* __restrict__ idx2,
    float* __restrict__ C, int M)
{
    constexpr int NCH = K / 32;
    constexpr int NST = 2 * NCH;
    extern __shared__ __align__(16) uint8_t sB[];
    uint8_t* sBhi = sB;
    uint8_t* sBlo = sB + NCH * CHB;

    const int tid = threadIdx.x;
    const int wid = tid >> 5;
    const int lid = tid & 31;
    const int m0  = blockIdx.x * 128;

    {
        const int frow = tid >> 1;
        const int fkh  = (tid & 1) * 16;
#pragma unroll
        for (int c = 0; c < NCH; c++) {
            const __nv_bfloat16* sh = Whi + (size_t)frow * K + c * 32 + fkh;
            const __nv_bfloat16* sl = Wlo + (size_t)frow * K + c * 32 + fkh;
            const uint32_t off = c * CHB + frow * PITCH + fkh * 2;
            *(uint4*)(sBhi + off)      = *(const uint4*)sh;
            *(uint4*)(sBhi + off + 16) = *(const uint4*)(sh + 8);
            *(uint4*)(sBlo + off)      = *(const uint4*)sl;
            *(uint4*)(sBlo + off + 16) = *(const uint4*)(sl + 8);
        }
    }
    __syncthreads();

    const int q   = lid >> 2;
    const int c2  = (lid & 3) * 2;
    const int r0g = m0 + wid * 16 + q;
    int ar0 = min(r0g,     M - 1);
    int ar1 = min(r0g + 8, M - 1);
    if (GATHER) { ar0 = gidx[ar0]; ar1 = gidx[ar1]; }
    const float* Arow0 = A + (size_t)ar0 * K;
    const float* Arow1 = A + (size_t)ar1 * K;

    const int r8 = lid & 7, jj = lid >> 3;
    const uint32_t offB = (uint32_t)(((jj >> 1) * 8 + r8) * PITCH + (jj & 1) * 16);
    const uint32_t uBhi = smem_u32(sBhi);
    const uint32_t uBlo = smem_u32(sBlo);

    float acc[16][4];
#pragma unroll
    for (int j = 0; j < 16; j++)
#pragma unroll
        for (int i = 0; i < 4; i++) acc[j][i] = 0.f;

    float2 pf0, pf1, pf2, pf3;
    pf0 = *(const float2*)(Arow0 + c2);
    pf1 = *(const float2*)(Arow1 + c2);
    pf2 = *(const float2*)(Arow0 + c2 + 8);
    pf3 = *(const float2*)(Arow1 + c2 + 8);

#pragma unroll
    for (int step = 0; step < NST; step++) {
        uint32_t ah[4], al[4];
        cvt2(pf0, ah[0], al[0]);
        cvt2(pf1, ah[1], al[1]);
        cvt2(pf2, ah[2], al[2]);
        cvt2(pf3, ah[3], al[3]);
        if (step + 1 < NST) {
            const int k0 = (step + 1) * 16 + c2;
            pf0 = *(const float2*)(Arow0 + k0);
            pf1 = *(const float2*)(Arow1 + k0);
            pf2 = *(const float2*)(Arow0 + k0 + 8);
            pf3 = *(const float2*)(Arow1 + k0 + 8);
        }
        const uint32_t cb  = (uint32_t)(step >> 1) * CHB;
        const uint32_t kso = (uint32_t)(step & 1) * 32;
#pragma unroll
        for (int nb = 0; nb < 8; nb++) {
            uint32_t bh[4], bl[4];
            ldsm4(bh, uBhi + cb + offB + nb * (16 * PITCH) + kso);
            ldsm4(bl, uBlo + cb + offB + nb * (16 * PITCH) + kso);
            mma16816(acc[2 * nb],     ah, bh[0], bh[1]);
            mma16816(acc[2 * nb + 1], ah, bh[2], bh[3]);
            mma16816(acc[2 * nb],     ah, bl[0], bl[1]);
            mma16816(acc[2 * nb + 1], ah, bl[2], bl[3]);
            mma16816(acc[2 * nb],     al, bh[0], bh[1]);
            mma16816(acc[2 * nb + 1], al, bh[2], bh[3]);
        }
    }

#pragma unroll
    for (int h = 0; h < 2; h++) {
        const int r = m0 + wid * 16 + q + h * 8;
        if (r < M) {
            const float* g1 = nullptr;
            const float* g2 = nullptr;
            if (EPI >= 3) {
                g1 = G1 + (size_t)idx1[r] * HH;
                g2 = G2 + (size_t)idx2[r] * HH;
            }
            float* cp = C + (size_t)r * HH;
#pragma unroll
            for (int j = 0; j < 16; j++) {
                const int n0 = j * 8 + c2;
                float v0 = acc[j][h * 2 + 0] + bias[n0];
                float v1 = acc[j][h * 2 + 1] + bias[n0 + 1];
                if (EPI >= 3) {
                    v0 += g1[n0] + g2[n0];
                    v1 += g1[n0 + 1] + g2[n0 + 1];
                }
                if (EPI == 4) { v0 = fmaxf(v0, 0.f); v1 = fmaxf(v1, 0.f); }
                if (EPI == 2) {
                    float2 prev = *(float2*)(cp + n0);
                    v0 = prev.x + 0.5f * v0;
                    v1 = prev.y + 0.5f * v1;
                }
                *(float2*)(cp + n0) = make_float2(v0, v1);
            }
        }
    }
}

// ---------------- dual-output resident-B GEMM (K=128, 512 thr) ----------------
__global__ __launch_bounds__(512) void tcgN_dual(
    const float* __restrict__ A,
    const __nv_bfloat16* __restrict__ W1hi, const __nv_bfloat16* __restrict__ W1lo,
    const __nv_bfloat16* __restrict__ W2hi, const __nv_bfloat16* __restrict__ W2lo,
    const float* __restrict__ b1, const float* __restrict__ b2,
    float* __restrict__ C1, float* __restrict__ C2, int M)
{
    constexpr int K = 128, NCH = 4;
    extern __shared__ __align__(16) uint8_t sB[];
    const int tid = threadIdx.x;
    const int wid = tid >> 5;
    const int lid = tid & 31;
    const int m0  = blockIdx.x * 128;

    {
        const int frow = tid >> 2;
        const int fq   = tid & 3;
        const uint32_t wo = (uint32_t)frow * PITCH + fq * 16;
#pragma unroll
        for (int w = 0; w < 2; w++) {
            const __nv_bfloat16* Whi = w ? W2hi : W1hi;
            const __nv_bfloat16* Wlo = w ? W2lo : W1lo;
            uint8_t* dh = sB + w * (8 * CHB);
            uint8_t* dl = dh + 4 * CHB;
#pragma unroll
            for (int c = 0; c < NCH; c++) {
                const __nv_bfloat16* sh = Whi + (size_t)frow * K + c * 32 + fq * 8;
                const __nv_bfloat16* sl = Wlo + (size_t)frow * K + c * 32 + fq * 8;
                *(uint4*)(dh + c * CHB + wo) = *(const uint4*)sh;
                *(uint4*)(dl + c * CHB + wo) = *(const uint4*)sl;
            }
        }
    }
    __syncthreads();

    const int wsel = wid >> 3;
    const int w8   = wid & 7;
    const int q  = lid >> 2;
    const int c2 = (lid & 3) * 2;
    const int r0g = m0 + w8 * 16 + q;
    const size_t rc0 = (size_t)min(r0g,     M - 1);
    const size_t rc1 = (size_t)min(r0g + 8, M - 1);
    const float* Arow0 = A + rc0 * K;
    const float* Arow1 = A + rc1 * K;

    const int r8 = lid & 7, jj = lid >> 3;
    const uint32_t offB = (uint32_t)(((jj >> 1) * 8 + r8) * PITCH + (jj & 1) * 16);
    const uint32_t uBhi = smem_u32(sB) + wsel * (8 * CHB);
    const uint32_t uBlo = uBhi + 4 * CHB;

    float acc[16][4];
#pragma unroll
    for (int j = 0; j < 16; j++)
#pragma unroll
        for (int i = 0; i < 4; i++) acc[j][i] = 0.f;

    float2 pf0, pf1, pf2, pf3;
    pf0 = *(const float2*)(Arow0 + c2);
    pf1 = *(const float2*)(Arow1 + c2);
    pf2 = *(const float2*)(Arow0 + c2 + 8);
    pf3 = *(const float2*)(Arow1 + c2 + 8);
#pragma unroll
    for (int step = 0; step < 8; step++) {
        uint32_t ah[4], al[4];
        cvt2(pf0, ah[0], al[0]);
        cvt2(pf1, ah[1], al[1]);
        cvt2(pf2, ah[2], al[2]);
        cvt2(pf3, ah[3], al[3]);
        if (step + 1 < 8) {
            const int k0 = (step + 1) * 16 + c2;
            pf0 = *(const float2*)(Arow0 + k0);
            pf1 = *(const float2*)(Arow1 + k0);
            pf2 = *(const float2*)(Arow0 + k0 + 8);
            pf3 = *(const float2*)(Arow1 + k0 + 8);
        }
        const uint32_t cb  = (uint32_t)(step >> 1) * CHB;
        const uint32_t kso = (uint32_t)(step & 1) * 32;
#pragma unroll
        for (int nb = 0; nb < 8; nb++) {
            uint32_t bh[4], bl[4];
            ldsm4(bh, uBhi + cb + offB + nb * (16 * PITCH) + kso);
            ldsm4(bl, uBlo + cb + offB + nb * (16 * PITCH) + kso);
            mma16816(acc[2 * nb],     ah, bh[0], bh[1]);
            mma16816(acc[2 * nb + 1], ah, bh[2], bh[3]);
            mma16816(acc[2 * nb],     ah, bl[0], bl[1]);
            mma16816(acc[2 * nb + 1], ah, bl[2], bl[3]);
            mma16816(acc[2 * nb],     al, bh[0], bh[1]);
            mma16816(acc[2 * nb + 1], al, bh[2], bh[3]);
        }
    }

    const float* bias = wsel ? b2 : b1;
    float* C = wsel ? C2 : C1;
#pragma unroll
    for (int h = 0; h < 2; h++) {
        const int r = m0 + w8 * 16 + q + h * 8;
        if (r < M) {
            float* cp = C + (size_t)r * HH;
#pragma unroll
            for (int j = 0; j < 16; j++) {
                const int n0 = j * 8 + c2;
                *(float2*)(cp + n0) = make_float2(acc[j][h * 2 + 0] + bias[n0],
                                                  acc[j][h * 2 + 1] + bias[n0 + 1]);
            }
        }
    }
}

// ---------------- chunked pipeline GEMM over VIRTUAL pin (K=1664) ----------------
// A row k-space: [0,128)=X[r], [128,640)=AGG[r], [640,1152)=amp*AGG[r], [1152,1664)=att*AGG[r]
__global__ __launch_bounds__(256) void tcg_big_virt(
    const float* __restrict__ X, const float* __restrict__ AGG,
    const float2* __restrict__ SC,
    const __nv_bfloat16* __restrict__ Whi, const __nv_bfloat16* __restrict__ Wlo,
    const float* __restrict__ bias, float* __restrict__ C, int M)
{
    constexpr int K = 1664;
    __shared__ __align__(16) uint8_t sAhi[128 * PITCH];
    __shared__ __align__(16) uint8_t sAlo[128 * PITCH];
    __shared__ __align__(16) uint8_t sBhi[128 * PITCH];
    __shared__ __align__(16) uint8_t sBlo[128 * PITCH];

    const int tid = threadIdx.x;
    const int wid = tid >> 5;
    const int lid = tid & 31;
    const int m0  = blockIdx.x * 128;

    const int frow = tid >> 1;
    const int fkh  = (tid & 1) * 16;
    const int ar   = min(m0 + frow, M - 1);
    const float* Xrow = X + (size_t)ar * HH;
    const float* Arow = AGG + (size_t)ar * (4 * HH);
    const float2 sc = SC[ar];
    const __nv_bfloat16* bhRow = Whi + (size_t)frow * K;
    const __nv_bfloat16* blRow = Wlo + (size_t)frow * K;
    uint8_t* aHiDst = sAhi + frow * PITCH + fkh * 2;
    uint8_t* aLoDst = sAlo + frow * PITCH + fkh * 2;
    uint8_t* bHiDst = sBhi + frow * PITCH + fkh * 2;
    uint8_t* bLoDst = sBlo + frow * PITCH + fkh * 2;

    const int r8 = lid & 7, jj = lid >> 3;
    const uint32_t offA = (uint32_t)(((jj & 1) * 8 + r8 + wid * 16) * PITCH + (jj >> 1) * 16);
    const uint32_t offB = (uint32_t)(((jj >> 1) * 8 + r8) * PITCH + (jj & 1) * 16);
    const uint32_t uAhi = smem_u32(sAhi), uAlo = smem_u32(sAlo);
    const uint32_t uBhi = smem_u32(sBhi), uBlo = smem_u32(sBlo);

    float acc[16][4];
#pragma unroll
    for (int j = 0; j < 16; j++)
#pragma unroll
        for (int i = 0; i < 4; i++) acc[j][i] = 0.f;

    for (int kc = 0; kc < K; kc += 32) {
        const int k0 = kc + fkh;
        const float* p;
        float s;
        if (k0 < 128)       { p = Xrow + k0;          s = 1.f; }
        else if (k0 < 640)  { p = Arow + (k0 - 128);  s = 1.f; }
        else if (k0 < 1152) { p = Arow + (k0 - 640);  s = sc.x; }
        else                { p = Arow + (k0 - 1152); s = sc.y; }
        float4 f0 = *(const float4*)(p + 0);
        float4 f1 = *(const float4*)(p + 4);
        float4 f2 = *(const float4*)(p + 8);
        float4 f3 = *(const float4*)(p + 12);
        uint4 bh0 = *(const uint4*)(bhRow + kc + fkh);
        uint4 bh1 = *(const uint4*)(bhRow + kc + fkh + 8);
        uint4 bl0 = *(const uint4*)(blRow + kc + fkh);
        uint4 bl1 = *(const uint4*)(blRow + kc + fkh + 8);

        float f[16] = {f0.x * s, f0.y * s, f0.z * s, f0.w * s,
                       f1.x * s, f1.y * s, f1.z * s, f1.w * s,
                       f2.x * s, f2.y * s, f2.z * s, f2.w * s,
                       f3.x * s, f3.y * s, f3.z * s, f3.w * s};
        uint32_t hw[8], lw[8];
#pragma unroll
        for (int i = 0; i < 8; i++) {
            float2 pp = make_float2(f[2 * i], f[2 * i + 1]);
            cvt2(pp, hw[i], lw[i]);
        }

        __syncthreads();
        *(uint4*)(aHiDst)      = make_uint4(hw[0], hw[1], hw[2], hw[3]);
        *(uint4*)(aHiDst + 16) = make_uint4(hw[4], hw[5], hw[6], hw[7]);
        *(uint4*)(aLoDst)      = make_uint4(lw[0], lw[1], lw[2], lw[3]);
        *(uint4*)(aLoDst + 16) = make_uint4(lw[4], lw[5], lw[6], lw[7]);
        *(uint4*)(bHiDst)      = bh0;
        *(uint4*)(bHiDst + 16) = bh1;
        *(uint4*)(bLoDst)      = bl0;
        *(uint4*)(bLoDst + 16) = bl1;
        __syncthreads();

#pragma unroll
        for (int ks = 0; ks < 2; ks++) {
            const uint32_t kso = ks * 32;
            uint32_t ah[4], al[4];
            ldsm4(ah, uAhi + offA + kso);
            ldsm4(al, uAlo + offA + kso);
#pragma unroll
            for (int nb = 0; nb < 8; nb++) {
                uint32_t bh[4], bl[4];
                ldsm4(bh, uBhi + offB + nb * (16 * PITCH) + kso);
                ldsm4(bl, uBlo + offB + nb * (16 * PITCH) + kso);
                mma16816(acc[2 * nb],     ah, bh[0], bh[1]);
                mma16816(acc[2 * nb + 1], ah, bh[2], bh[3]);
                mma16816(acc[2 * nb],     ah, bl[0], bl[1]);
                mma16816(acc[2 * nb + 1], ah, bl[2], bl[3]);
                mma16816(acc[2 * nb],     al, bh[0], bh[1]);
                mma16816(acc[2 * nb + 1], al, bh[2], bh[3]);
            }
        }
    }

    const int q  = lid >> 2;
    const int c2 = (lid & 3) * 2;
#pragma unroll
    for (int h = 0; h < 2; h++) {
        const int r = m0 + wid * 16 + q + h * 8;
        if (r < M) {
            float* cp = C + (size_t)r * HH;
#pragma unroll
            for (int j = 0; j < 16; j++) {
                const int n0 = j * 8 + c2;
                *(float2*)(cp + n0) = make_float2(acc[j][h * 2 + 0] + bias[n0],
                                                  acc[j][h * 2 + 1] + bias[n0 + 1]);
            }
        }
    }
}

// ---------------- batched weight prep ----------------
#define NJOBS 13
struct PrepJobs {
    const float* W[NJOBS];
    __nv_bfloat16* hi[NJOBS];
    __nv_bfloat16* lo[NJOBS];
    int K[NJOBS];
};
__global__ void prep_all_kernel(PrepJobs jobs) {
    const int job = blockIdx.y;
    const int K = jobs.K[job];
    const int i = blockIdx.x * 256 + threadIdx.x;
    if (i >= K * 128) return;
    const int k = i >> 7, n = i & 127;
    float w = jobs.W[job][i];
    __nv_bfloat16 h = __float2bfloat16(w);
    float rem = w - __bfloat162float(h);
    jobs.hi[job][(size_t)n * K + k] = h;
    jobs.lo[job][(size_t)n * K + k] = __float2bfloat16(rem);
}

__global__ void combine_wc_kernel(const float* __restrict__ eenc_w,
                                  const float* __restrict__ pre_w,
                                  __nv_bfloat16* __restrict__ hi,
                                  __nv_bfloat16* __restrict__ lo) {
    const int l = blockIdx.y;
    const float* ew = eenc_w + (size_t)l * 128 * 128;
    const float* W3 = pre_w + (size_t)l * 384 * 128 + 256 * 128;
    int i = blockIdx.x * blockDim.x + threadIdx.x;
    int k = i >> 7, n = i & 127;
    float s = 0.f;
    for (int j = 0; j < 128; j++) s += ew[k * 128 + j] * W3[j * 128 + n];
    __nv_bfloat16 h = __float2bfloat16(s);
    float rem = s - __bfloat162float(h);
    size_t o = (size_t)l * 128 * 128;
    hi[o + (size_t)n * 128 + k] = h;
    lo[o + (size_t)n * 128 + k] = __float2bfloat16(rem);
}
__global__ void combine_bc_kernel(const float* __restrict__ eenc_b,
                                  const float* __restrict__ pre_w,
                                  const float* __restrict__ pre_b,
                                  float* __restrict__ bc, float* __restrict__ zv) {
    const int l = blockIdx.x;
    const float* W3 = pre_w + (size_t)l * 384 * 128 + 256 * 128;
    int n = threadIdx.x;
    float s = pre_b[l * 128 + n];
    for (int j = 0; j < 128; j++) s += eenc_b[l * 128 + j] * W3[j * 128 + n];
    bc[l * 128 + n] = s;
    if (l == 0) zv[n] = 0.f;
}
__global__ void combine_pl_kernel(const float* __restrict__ post_w,
                                  const float* __restrict__ lin_w,
                                  __nv_bfloat16* __restrict__ hi,
                                  __nv_bfloat16* __restrict__ lo) {
    const int l = blockIdx.y;
    const float* pw = post_w + (size_t)l * 1664 * 128;
    const float* lw = lin_w + (size_t)l * 128 * 128;
    int i = blockIdx.x * blockDim.x + threadIdx.x;
    if (i >= 1664 * 128) return;
    int k = i >> 7, n = i & 127;
    float s = 0.f;
    for (int j = 0; j < 128; j++) s += pw[(size_t)k * 128 + j] * lw[j * 128 + n];
    __nv_bfloat16 h = __float2bfloat16(s);
    float rem = s - __bfloat162float(h);
    size_t o = (size_t)l * 128 * 1664;
    hi[o + (size_t)n * 1664 + k] = h;
    lo[o + (size_t)n * 1664 + k] = __float2bfloat16(rem);
}
__global__ void combine_bpl_kernel(const float* __restrict__ post_b,
                                   const float* __restrict__ lin_w,
                                   const float* __restrict__ lin_b,
                                   float* __restrict__ bpl) {
    const int l = blockIdx.x;
    const float* lw = lin_w + (size_t)l * 128 * 128;
    int n = threadIdx.x;
    float s = lin_b[l * 128 + n];
    for (int j = 0; j < 128; j++) s += post_b[l * 128 + j] * lw[j * 128 + n];
    bpl[l * 128 + n] = s;
}

// ---------------- CSR build + edge permutation ----------------
__global__ void zero_cnt_we_kernel(const float* __restrict__ We) {
    int i = blockIdx.x * blockDim.x + threadIdx.x;
    if (i < NN) g_cnt[i] = 0;
    if (i < EDD * 128) {
        int k = i >> 7, n = i & 127;
        float w = We[i];
        __nv_bfloat16 h = __float2bfloat16(w);
        float rem = w - __bfloat162float(h);
        g_we_hi[(size_t)n * EDD + k] = h;
        g_we_lo[(size_t)n * EDD + k] = __float2bfloat16(rem);
    }
}
__global__ void hist_kernel(const int* __restrict__ dst) {
    int e = blockIdx.x * blockDim.x + threadIdx.x;
    if (e < EE) atomicAdd(&g_cnt[dst[e]], 1);
}
__global__ void scan1_kernel() {
    __shared__ int s[1024];
    int t = threadIdx.x, i = blockIdx.x * 1024 + t;
    int v = (i < NN) ? g_cnt[i] : 0;
    s[t] = v;
    __syncthreads();
    for (int off = 1; off < 1024; off <<= 1) {
        int y = (t >= off) ? s[t - off] : 0;
        __syncthreads();
        s[t] += y;
        __syncthreads();
    }
    if (i < NN) g_rowptr[i] = s[t] - v;
    if (t == 1023) g_blksum[blockIdx.x] = s[1023];
}
__global__ void scan23_kernel() {
    __shared__ int base;
    if (threadIdx.x == 0) {
        int run = 0;
        for (int b = 0; b < (int)blockIdx.x; b++) run += g_blksum[b];
        base = run;
    }
    __syncthreads();
    int i = blockIdx.x * 1024 + threadIdx.x;
    if (i < NN) {
        int r = g_rowptr[i] + base;
        g_rowptr[i] = r;
        g_wr[i] = r;
    }
    if (i == 0) g_rowptr[NN] = EE;
}
__global__ void scatter_kernel(const int* __restrict__ src, const int* __restrict__ dst) {
    int e = blockIdx.x * blockDim.x + threadIdx.x;
    if (e < EE) {
        int d = dst[e];
        int o = atomicAdd(&g_wr[d], 1);
        g_eord[o] = e;
        g_psrc[o] = src[e];
        g_pdst[o] = d;
    }
}

// ---------------- fused streaming segmented reduce -> compact agg + scales -------
__global__ void agg_pin_kernel(const float* __restrict__ adl_ptr) {
    const int n = blockIdx.x;
    const int c = threadIdx.x;
    const int a = g_rowptr[n], b = g_rowptr[n + 1];
    float sum = 0.f, ss = 0.f, mn = FLT_MAX, mx = -FLT_MAX;
    for (int i = a; i < b; i++) {
        float v = g_h[(size_t)i * HH + c];
        sum += v;
        ss  += v * v;
        mn = fminf(mn, v);
        mx = fmaxf(mx, v);
    }
    float deg  = (float)(b - a);
    float degc = fmaxf(deg, 1.f);
    float adl  = *adl_ptr;
    float logd = logf(degc + 1.f);
    if (deg <= 0.f) { mn = 0.f; mx = 0.f; }
    float mean = sum / degc;
    float var  = ss / degc - mean * mean;
    float stdv = sqrtf(fmaxf(var, 0.f) + 1e-5f);
    float* r = g_agg + (size_t)n * (4 * HH);
    r[0 * HH + c] = mean;
    r[1 * HH + c] = mn;
    r[2 * HH + c] = mx;
    r[3 * HH + c] = stdv;
    if (c == 0) g_scale[n] = make_float2(logd / adl, adl / logd);
}

// ---------------- batchnorm + residual ----------------
__global__ void bn_zero_kernel() {
    if (threadIdx.x < HH) { g_bnsum[threadIdx.x] = 0.f; g_bnss[threadIdx.x] = 0.f; }
}
__global__ void bn_reduce_kernel() {
    int c  = threadIdx.x;
    int r0 = blockIdx.x * 128;
    int r1 = min(r0 + 128, NN);
    float s = 0.f, ss = 0.f;
    for (int r = r0; r < r1; r++) {
        float v = g_out[(size_t)r * HH + c];
        s += v; ss += v * v;
    }
    atomicAdd(&g_bnsum[c], s);
    atomicAdd(&g_bnss[c], ss);
}
__global__ void bn_apply_kernel(const float* __restrict__ gamma,
                                const float* __restrict__ beta,
                                float* __restrict__ xout) {
    size_t idx = (size_t)blockIdx.x * blockDim.x + threadIdx.x;
    if (idx >= (size_t)NN * HH) return;
    int c = (int)(idx & 127);
    float mu  = g_bnsum[c] / (float)NN;
    float var = g_bnss[c] / (float)NN - mu * mu;
    float v = gamma[c] * (g_out[idx] - mu) * rsqrtf(var + 1e-5f) + beta[c];
    float r = (g_x[idx] + fmaxf(v, 0.f)) * 0.5f;
    g_x[idx] = r;
    if (xout) xout[idx] = r;
}

// ---------------- launch ----------------
extern "C" void kernel_launch(void* const* d_in, const int* in_sizes, int n_in,
                              void* d_out, int out_size) {
    (void)in_sizes; (void)n_in; (void)out_size;

    const float* x_in     = (const float*)d_in[0];
    const int*   ei       = (const int*)  d_in[1];
    const float* eattr    = (const float*)d_in[2];
    const float* pos_attr = (const float*)d_in[4];
    const float* neg_attr = (const float*)d_in[6];
    const float* adl      = (const float*)d_in[7];
    const float* Wnode    = (const float*)d_in[8];
    const float* bnode    = (const float*)d_in[9];
    const float* Wedge    = (const float*)d_in[10];
    const float* bedge    = (const float*)d_in[11];
    const float* eenc_w   = (const float*)d_in[12];
    const float* eenc_b   = (const float*)d_in[13];
    const float* pre_w    = (const float*)d_in[14];
    const float* pre_b    = (const float*)d_in[15];
    const float* post_w   = (const float*)d_in[16];
    const float* post_b   = (const float*)d_in[17];
    const float* lin_w    = (const float*)d_in[18];
    const float* lin_b    = (const float*)d_in[19];
    const float* emlp_w1  = (const float*)d_in[20];
    const float* emlp_b1  = (const float*)d_in[21];
    const float* emlp_w2  = (const float*)d_in[22];
    const float* emlp_b2  = (const float*)d_in[23];
    const float* bng      = (const float*)d_in[24];
    const float* bnb      = (const float*)d_in[25];

    const int* src = ei;
    const int* dst = ei + EE;

    float* outx   = (float*)d_out;
    float* outpos = outx + (size_t)NN * HH;
    float* outneg = outpos + (size_t)EPP * HH;

    float *p_x, *p_ea, *p_h, *p_agg, *p_out, *p_pa, *p_pb, *p_zero, *p_bc, *p_bpl;
    float2* p_sc;
    cudaGetSymbolAddress((void**)&p_x,    g_x);
    cudaGetSymbolAddress((void**)&p_ea,   g_ea);
    cudaGetSymbolAddress((void**)&p_h,    g_h);
    cudaGetSymbolAddress((void**)&p_agg,  g_agg);
    cudaGetSymbolAddress((void**)&p_sc,   g_scale);
    cudaGetSymbolAddress((void**)&p_out,  g_out);
    cudaGetSymbolAddress((void**)&p_pa,   g_pa);
    cudaGetSymbolAddress((void**)&p_pb,   g_pb);
    cudaGetSymbolAddress((void**)&p_zero, g_zerov);
    cudaGetSymbolAddress((void**)&p_bc,   g_bc);
    cudaGetSymbolAddress((void**)&p_bpl,  g_bpl);

    int *p_eord, *p_psrc, *p_pdst;
    cudaGetSymbolAddress((void**)&p_eord, g_eord);
    cudaGetSymbolAddress((void**)&p_psrc, g_psrc);
    cudaGetSymbolAddress((void**)&p_pdst, g_pdst);

    __nv_bfloat16 *wn_h, *wn_l, *we_h, *we_l;
    __nv_bfloat16 *wc_h, *wc_l, *w1_h, *w1_l, *w2_h, *w2_l;
    __nv_bfloat16 *u1_h, *u1_l, *u2_h, *u2_l, *u3_h, *u3_l;
    __nv_bfloat16 *e2_h, *e2_l, *pl_h, *pl_l;
    cudaGetSymbolAddress((void**)&wn_h, g_wn_hi);  cudaGetSymbolAddress((void**)&wn_l, g_wn_lo);
    cudaGetSymbolAddress((void**)&we_h, g_we_hi);  cudaGetSymbolAddress((void**)&we_l, g_we_lo);
    cudaGetSymbolAddress((void**)&wc_h, g_wc_hi);  cudaGetSymbolAddress((void**)&wc_l, g_wc_lo);
    cudaGetSymbolAddress((void**)&w1_h, g_w1_hi);  cudaGetSymbolAddress((void**)&w1_l, g_w1_lo);
    cudaGetSymbolAddress((void**)&w2_h, g_w2_hi);  cudaGetSymbolAddress((void**)&w2_l, g_w2_lo);
    cudaGetSymbolAddress((void**)&u1_h, g_u1_hi);  cudaGetSymbolAddress((void**)&u1_l, g_u1_lo);
    cudaGetSymbolAddress((void**)&u2_h, g_u2_hi);  cudaGetSymbolAddress((void**)&u2_l, g_u2_lo);
    cudaGetSymbolAddress((void**)&u3_h, g_u3_hi);  cudaGetSymbolAddress((void**)&u3_l, g_u3_lo);
    cudaGetSymbolAddress((void**)&e2_h, g_em2_hi); cudaGetSymbolAddress((void**)&e2_l, g_em2_lo);
    cudaGetSymbolAddress((void**)&pl_h, g_pl_hi);  cudaGetSymbolAddress((void**)&pl_l, g_pl_lo);

    const int SM128 = 2 * 4 * CHB;
    const int SM64  = 2 * 2 * CHB;
    const int SM32  = 2 * 1 * CHB;
    const int SMD   = 4 * 4 * CHB;
    cudaFuncSetAttribute(tcgN<128, 2, false>, cudaFuncAttributeMaxDynamicSharedMemorySize, SM128);
    cudaFuncSetAttribute(tcgN<128, 3, false>, cudaFuncAttributeMaxDynamicSharedMemorySize, SM128);
    cudaFuncSetAttribute(tcgN<128, 4, false>, cudaFuncAttributeMaxDynamicSharedMemorySize, SM128);
    cudaFuncSetAttribute(tcgN<64, 0, false>,  cudaFuncAttributeMaxDynamicSharedMemorySize, SM64);
    cudaFuncSetAttribute(tcgN<32, 0, false>,  cudaFuncAttributeMaxDynamicSharedMemorySize, SM32);
    cudaFuncSetAttribute(tcgN<32, 0, true>,   cudaFuncAttributeMaxDynamicSharedMemorySize, SM32);
    cudaFuncSetAttribute(tcgN_dual,           cudaFuncAttributeMaxDynamicSharedMemorySize, SMD);

    const int GB_E  = EE / 128;
    const int GB_N  = (NN + 127) / 128;
    const int GB_EP = (EPP + 127) / 128;
    const int G_NH  = (int)(((size_t)NN * HH + 255) / 256);
    const int NBLK  = (NN + 1023) / 1024;

    // ---- CSR build (+ Wedge conversion folded into launch 0) ----
    zero_cnt_we_kernel<<<(NN + 255) / 256, 256>>>(Wedge);
    hist_kernel<<<(EE + 255) / 256, 256>>>(dst);
    scan1_kernel<<<NBLK, 1024>>>();
    scan23_kernel<<<NBLK, 1024>>>();
    scatter_kernel<<<(EE + 255) / 256, 256>>>(src, dst);

    // ---- ea embedding (dst-sorted order via gather) ----
    tcgN<32, 0, true><<<GB_E, 256, SM32>>>(eattr, p_eord, we_h, we_l, bedge,
        nullptr, nullptr, nullptr, nullptr, p_ea, EE);

    // ---- weight prep ----
    {
        PrepJobs jobs;
        int j = 0;
        jobs.W[j] = Wnode; jobs.hi[j] = wn_h; jobs.lo[j] = wn_l; jobs.K[j] = 64; j++;
        for (int l = 0; l < LLAYERS; l++) {
            const float* preW = pre_w + (size_t)l * 384 * 128;
            const float* em1W = emlp_w1 + (size_t)l * 384 * 128;
            size_t o = (size_t)l * 128 * 128;
            jobs.W[j] = preW;            jobs.hi[j] = w1_h + o; jobs.lo[j] = w1_l + o; jobs.K[j] = 128; j++;
            jobs.W[j] = preW + 128*128;  jobs.hi[j] = w2_h + o; jobs.lo[j] = w2_l + o; jobs.K[j] = 128; j++;
            jobs.W[j] = em1W;            jobs.hi[j] = u1_h + o; jobs.lo[j] = u1_l + o; jobs.K[j] = 128; j++;
            jobs.W[j] = em1W + 128*128;  jobs.hi[j] = u2_h + o; jobs.lo[j] = u2_l + o; jobs.K[j] = 128; j++;
            jobs.W[j] = em1W + 256*128;  jobs.hi[j] = u3_h + o; jobs.lo[j] = u3_l + o; jobs.K[j] = 128; j++;
            jobs.W[j] = emlp_w2 + o;     jobs.hi[j] = e2_h + o; jobs.lo[j] = e2_l + o; jobs.K[j] = 128; j++;
        }
        dim3 grid((128 * 128 + 255) / 256, NJOBS);
        prep_all_kernel<<<grid, 256>>>(jobs);
    }
    {
        dim3 gwc(64, LLAYERS);
        combine_wc_kernel<<<gwc, 256>>>(eenc_w, pre_w, wc_h, wc_l);
        combine_bc_kernel<<<LLAYERS, 128>>>(eenc_b, pre_w, pre_b, p_bc, p_zero);
        dim3 gpl((1664 * 128 + 255) / 256, LLAYERS);
        combine_pl_kernel<<<gpl, 256>>>(post_w, lin_w, pl_h, pl_l);
        combine_bpl_kernel<<<LLAYERS, 128>>>(post_b, lin_w, lin_b, p_bpl);
    }

    // ---- remaining embeddings ----
    tcgN<64, 0, false><<<GB_N, 256, SM64>>>(x_in, nullptr, wn_h, wn_l, bnode,
        nullptr, nullptr, nullptr, nullptr, p_x, NN);
    tcgN<32, 0, false><<<GB_EP, 256, SM32>>>(pos_attr, nullptr, we_h, we_l, bedge,
        nullptr, nullptr, nullptr, nullptr, outpos, EPP);
    tcgN<32, 0, false><<<GB_EP, 256, SM32>>>(neg_attr, nullptr, we_h, we_l, bedge,
        nullptr, nullptr, nullptr, nullptr, outneg, EPP);

    for (int l = 0; l < LLAYERS; l++) {
        size_t o = (size_t)l * 128 * 128;
        // node partials P1 = x@W1^T + bc, P2 = x@W2^T
        tcgN_dual<<<GB_N, 512, SMD>>>(p_x, w1_h + o, w1_l + o, w2_h + o, w2_l + o,
                                      p_bc + l * 128, p_zero, p_pa, p_pb, NN);
        // h = ea@Wc^T + P1[pdst] + P2[psrc]
        tcgN<128, 3, false><<<GB_E, 256, SM128>>>(p_ea, nullptr, wc_h + o, wc_l + o, p_zero,
            p_pa, p_pdst, p_pb, p_psrc, p_h, EE);
        // streaming segmented reduce -> compact agg + per-node scales
        agg_pin_kernel<<<NN, 128>>>(adl);
        // out = virtual_pin @ (post@lin)^T + b_pl
        tcg_big_virt<<<GB_N, 256>>>(p_x, p_agg, p_sc,
                                    pl_h + (size_t)l * 128 * 1664,
                                    pl_l + (size_t)l * 128 * 1664,
                                    p_bpl + l * HH, p_out, NN);
        // batchnorm + residual
        bn_zero_kernel<<<1, 128>>>();
        bn_reduce_kernel<<<GB_N, 128>>>();
        bn_apply_kernel<<<G_NH, 256>>>(bng + l * HH, bnb + l * HH,
                                       (l == LLAYERS - 1) ? outx : nullptr);
        // edge update
        tcgN_dual<<<GB_N, 512, SMD>>>(p_x, u1_h + o, u1_l + o, u2_h + o, u2_l + o,
                                      emlp_b1 + l * HH, p_zero, p_pa, p_pb, NN);
        tcgN<128, 4, false><<<GB_E, 256, SM128>>>(p_ea, nullptr, u3_h + o, u3_l + o, p_zero,
            p_pa, p_psrc, p_pb, p_pdst, p_h, EE);
        tcgN<128, 2, false><<<GB_E, 256, SM128>>>(p_h, nullptr, e2_h + o, e2_l + o,
            emlp_b2 + l * HH, nullptr, nullptr, nullptr, nullptr, p_ea, EE);
    }
}